// round 15
// baseline (speedup 1.0000x reference)
#include <cuda_runtime.h>
#include <cuda_bf16.h>
#include <math.h>
#include <stdint.h>

using bf16 = __nv_bfloat16;

constexpr int SEQ    = 4096;
constexpr int DMODEL = 768;
constexpr int NH     = 12;
constexpr int DH     = 64;
constexpr int HALF   = DH / 2;   // 32
constexpr int WELEM  = DMODEL * DMODEL;

// Q pre-scale: (1/sqrt(64)) * log2(e)  -> softmax computed in exp2 domain
constexpr float QSCALE_LOG2 = 0.125f * 1.44269504088896340736f;

// attention work split: qb in [32,63] handled by 2 CTAs (KV halves) + merge
constexpr int QB_SPLIT   = 32;
constexpr int NSPLIT_CTA = (64 - QB_SPLIT) * NH * 2;   // 768
constexpr int NNORM_CTA  = QB_SPLIT * NH;              // 384

// Scratch (device globals; no runtime allocation allowed)
__device__ bf16  g_xh[SEQ * DMODEL];
__device__ bf16  g_xl[SEQ * DMODEL];
__device__ bf16  g_wh[4 * WELEM];
__device__ bf16  g_wl[4 * WELEM];
__device__ bf16  g_oh[SEQ * DMODEL];
__device__ bf16  g_ol[SEQ * DMODEL];
__device__ bf16  g_qh[NH * SEQ * DH];
__device__ bf16  g_ql[NH * SEQ * DH];
__device__ bf16  g_kh[NH * SEQ * DH];
__device__ bf16  g_kl[NH * SEQ * DH];
__device__ bf16  g_vh[NH * SEQ * DH];
__device__ bf16  g_vl[NH * SEQ * DH];
__device__ float g_cos[SEQ * HALF];
__device__ float g_sin[SEQ * HALF];
// split-KV partials: 768 slots x 64 rows x 64 cols + m/l per row
__device__ float g_po[NSPLIT_CTA * 64 * 64];
__device__ float g_pm[NSPLIT_CTA * 64];
__device__ float g_pl[NSPLIT_CTA * 64];
// split-K partials for the output projection
__device__ float g_pc[2 * SEQ * DMODEL];

// ---------------------------------------------------------------------------
// bf16 split helpers
// ---------------------------------------------------------------------------
__device__ __forceinline__ void split_store_pair(bf16* __restrict__ hi_arr,
                                                 bf16* __restrict__ lo_arr,
                                                 size_t idx, float a, float b)
{
    __nv_bfloat162 h = __floats2bfloat162_rn(a, b);
    float ha = __bfloat162float(h.x);
    float hb = __bfloat162float(h.y);
    __nv_bfloat162 l = __floats2bfloat162_rn(a - ha, b - hb);
    *reinterpret_cast<__nv_bfloat162*>(hi_arr + idx) = h;
    *reinterpret_cast<__nv_bfloat162*>(lo_arr + idx) = l;
}

__device__ __forceinline__ void splitpack(float a, float b,
                                          uint32_t& hi, uint32_t& lo)
{
    __nv_bfloat162 h = __floats2bfloat162_rn(a, b);
    float ha = __bfloat162float(h.x);
    float hb = __bfloat162float(h.y);
    __nv_bfloat162 l = __floats2bfloat162_rn(a - ha, b - hb);
    hi = *reinterpret_cast<uint32_t*>(&h);
    lo = *reinterpret_cast<uint32_t*>(&l);
}

__device__ __forceinline__ void cvt8_split(const float4& p0, const float4& p1,
                                           uint4& hi, uint4& lo)
{
    uint32_t h0, l0, h1, l1, h2, l2, h3, l3;
    splitpack(p0.x, p0.y, h0, l0);
    splitpack(p0.z, p0.w, h1, l1);
    splitpack(p1.x, p1.y, h2, l2);
    splitpack(p1.z, p1.w, h3, l3);
    hi = make_uint4(h0, h1, h2, h3);
    lo = make_uint4(l0, l1, l2, l3);
}

__device__ __forceinline__ float ex2f(float x)
{
    float y;
    asm("ex2.approx.ftz.f32 %0, %1;" : "=f"(y) : "f"(x));
    return y;
}

// ---------------------------------------------------------------------------
// One-time fp32 -> bf16 hi/lo conversion of x and the 4 weights + RoPE cache.
// grid.y: 0=x, 1..4=weights, 5=rope cache.
// ---------------------------------------------------------------------------
__global__ __launch_bounds__(256)
void convert_split_kernel(const float* __restrict__ x,
                          const float* __restrict__ wq, const float* __restrict__ wk,
                          const float* __restrict__ wv, const float* __restrict__ wo,
                          bf16* __restrict__ xh, bf16* __restrict__ xl,
                          bf16* __restrict__ wh, bf16* __restrict__ wl,
                          float* __restrict__ cc, float* __restrict__ ss)
{
    int y = blockIdx.y;
    if (y == 5) {
        int i = blockIdx.x * 256 + threadIdx.x;
        if (i >= SEQ * HALF) return;
        int p = i >> 5;
        int k = i & 31;
        float expo = -2.0f * (float)k / (float)DH;
        float invf = powf(10000.0f, expo);
        float ang  = (float)p * invf;
        cc[i] = cosf(ang);
        ss[i] = sinf(ang);
        return;
    }
    const float* src;
    bf16 *dh, *dl;
    int n;
    if (y == 0) { src = x;  dh = xh; dl = xl; n = SEQ * DMODEL; }
    else {
        src = (y == 1) ? wq : (y == 2) ? wk : (y == 3) ? wv : wo;
        dh = wh + (size_t)(y - 1) * WELEM;
        dl = wl + (size_t)(y - 1) * WELEM;
        n = WELEM;
    }
    int i = (blockIdx.x * 256 + threadIdx.x) * 8;
    if (i >= n) return;
    float4 a = *(const float4*)(src + i);
    float4 b = *(const float4*)(src + i + 4);
    uint4 hi, lo;
    cvt8_split(a, b, hi, lo);
    *(uint4*)(dh + i) = hi;
    *(uint4*)(dl + i) = lo;
}

// ---------------------------------------------------------------------------
// mma / ldmatrix / cp.async wrappers
// ---------------------------------------------------------------------------
__device__ __forceinline__ void ldsm4(uint32_t* r, uint32_t addr)
{
    asm volatile("ldmatrix.sync.aligned.m8n8.x4.shared.b16 {%0,%1,%2,%3}, [%4];"
        : "=r"(r[0]), "=r"(r[1]), "=r"(r[2]), "=r"(r[3]) : "r"(addr));
}
__device__ __forceinline__ void ldsm4t(uint32_t* r, uint32_t addr)
{
    asm volatile("ldmatrix.sync.aligned.m8n8.x4.trans.shared.b16 {%0,%1,%2,%3}, [%4];"
        : "=r"(r[0]), "=r"(r[1]), "=r"(r[2]), "=r"(r[3]) : "r"(addr));
}
__device__ __forceinline__ void mma16816(float* d, const uint32_t* a, const uint32_t* b)
{
    asm volatile(
        "mma.sync.aligned.m16n8k16.row.col.f32.bf16.bf16.f32 "
        "{%0,%1,%2,%3}, {%4,%5,%6,%7}, {%8,%9}, {%0,%1,%2,%3};"
        : "+f"(d[0]), "+f"(d[1]), "+f"(d[2]), "+f"(d[3])
        : "r"(a[0]), "r"(a[1]), "r"(a[2]), "r"(a[3]), "r"(b[0]), "r"(b[1]));
}
__device__ __forceinline__ void cp16(uint32_t dst, const void* src)
{
    asm volatile("cp.async.cg.shared.global [%0], [%1], 16;"
        :: "r"(dst), "l"(src));
}
#define CP_COMMIT() asm volatile("cp.async.commit_group;")
#define CP_WAIT(n)  asm volatile("cp.async.wait_group %0;" :: "n"(n))

// ---------------------------------------------------------------------------
// Split-bf16 NT GEMM on pre-split inputs.
// MODE 1: QKV fused (z selects W), RoPE epilogue, split-store scatter.
// MODE 2: split-K output projection: z = K-half index, fp32 partial store.
// ---------------------------------------------------------------------------
template<int MODE>
__global__ __launch_bounds__(256, 2)
void gemm_bf(const bf16* __restrict__ Agh, const bf16* __restrict__ Agl,
             const bf16* __restrict__ Wgh, const bf16* __restrict__ Wgl,
             float* __restrict__ Cout,
             bf16* __restrict__ qh, bf16* __restrict__ ql,
             bf16* __restrict__ kh, bf16* __restrict__ kl,
             bf16* __restrict__ vh, bf16* __restrict__ vl,
             const int* __restrict__ pos,
             const float* __restrict__ cosc, const float* __restrict__ sinc)
{
    constexpr int KD  = 768;
    constexpr int NCH = KD / 32;  // 24
    extern __shared__ __align__(128) uint8_t sm[];
    const uint32_t smb = (uint32_t)__cvta_generic_to_shared(sm);

    const int tid  = threadIdx.x;
    const int wid  = tid >> 5;
    const int lane = tid & 31;
    const int z    = blockIdx.z;
    const bf16* Bgh = (MODE == 1) ? Wgh + (size_t)z * WELEM : Wgh;
    const bf16* Bgl = (MODE == 1) ? Wgl + (size_t)z * WELEM : Wgl;
    const int m0   = blockIdx.y * 128;
    const int n0   = blockIdx.x * 128;
    const int wm   = wid >> 1;
    const int wn   = wid & 1;

    const int c0 = (MODE == 2) ? z * (NCH / 2) : 0;
    const int c1 = (MODE == 2) ? c0 + (NCH / 2) : NCH;

    float acc[2][8][4];
    #pragma unroll
    for (int m = 0; m < 2; m++)
        #pragma unroll
        for (int n = 0; n < 8; n++)
            #pragma unroll
            for (int j = 0; j < 4; j++) acc[m][n][j] = 0.0f;

    auto cp_chunk = [&](int c, int s) {
        uint32_t base = smb + s * 32768;
        int kb = c * 32;
        #pragma unroll
        for (int it = 0; it < 2; it++) {
            int i   = it * 256 + tid;
            int row = i >> 2, o = i & 3;
            uint32_t off = (uint32_t)(row * 64 + ((o ^ (row & 3)) << 4));
            size_t ga = (size_t)(m0 + row) * KD + kb + o * 8;
            size_t gb = (size_t)(n0 + row) * KD + kb + o * 8;
            cp16(base + off,         Agh + ga);
            cp16(base +  8192 + off, Agl + ga);
            cp16(base + 16384 + off, Bgh + gb);
            cp16(base + 24576 + off, Bgl + gb);
        }
    };

    cp_chunk(c0, c0 % 3);         CP_COMMIT();
    cp_chunk(c0 + 1, (c0 + 1) % 3); CP_COMMIT();

    for (int c = c0; c < c1; c++) {
        if (c < c1 - 1) { CP_WAIT(1); } else { CP_WAIT(0); }
        __syncthreads();
        if (c + 2 < c1) { cp_chunk(c + 2, (c + 2) % 3); CP_COMMIT(); }

        const uint32_t sb = smb + (c % 3) * 32768;
        #pragma unroll
        for (int kt = 0; kt < 2; kt++) {
            uint32_t ah[2][4], al[2][4];
            #pragma unroll
            for (int m = 0; m < 2; m++) {
                int row = wm * 32 + m * 16 + (lane & 15);
                int ch  = kt * 2 + (lane >> 4);
                uint32_t off = (uint32_t)(row * 64 + ((ch ^ (row & 3)) << 4));
                ldsm4(ah[m], sb + off);
                ldsm4(al[m], sb + 8192 + off);
            }
            uint32_t bh4[4][4], bl4[4][4];
            #pragma unroll
            for (int np = 0; np < 4; np++) {
                int row = wn * 64 + np * 16 + (lane & 7) + ((lane >> 4) << 3);
                int ch  = kt * 2 + ((lane >> 3) & 1);
                uint32_t off = (uint32_t)(row * 64 + ((ch ^ (row & 3)) << 4));
                ldsm4(bh4[np], sb + 16384 + off);
                ldsm4(bl4[np], sb + 24576 + off);
            }
            #pragma unroll
            for (int m = 0; m < 2; m++)
                #pragma unroll
                for (int np = 0; np < 4; np++) {
                    mma16816(acc[m][2*np],     ah[m], bh4[np]);
                    mma16816(acc[m][2*np + 1], ah[m], bh4[np] + 2);
                }
            #pragma unroll
            for (int m = 0; m < 2; m++)
                #pragma unroll
                for (int np = 0; np < 4; np++) {
                    mma16816(acc[m][2*np],     ah[m], bl4[np]);
                    mma16816(acc[m][2*np + 1], ah[m], bl4[np] + 2);
                }
            #pragma unroll
            for (int m = 0; m < 2; m++)
                #pragma unroll
                for (int np = 0; np < 4; np++) {
                    mma16816(acc[m][2*np],     al[m], bh4[np]);
                    mma16816(acc[m][2*np + 1], al[m], bh4[np] + 2);
                }
        }
    }

    // ---- epilogue ----
    const int rbase = m0 + wm * 32 + (lane >> 2);
    const int cbase = n0 + wn * 64 + (lane & 3) * 2;

    if (MODE == 2) {
        float* dst = Cout + (size_t)z * SEQ * DMODEL;
        #pragma unroll
        for (int m = 0; m < 2; m++)
            #pragma unroll
            for (int nt = 0; nt < 8; nt++) {
                const float* v = acc[m][nt];
                int r = rbase + m * 16;
                int c = cbase + nt * 8;
                *(float2*)&dst[(size_t)r * DMODEL + c]       = make_float2(v[0], v[1]);
                *(float2*)&dst[(size_t)(r + 8) * DMODEL + c] = make_float2(v[2], v[3]);
            }
    } else {
        bf16* hi_arr = (z == 0) ? qh : (z == 1) ? kh : vh;
        bf16* lo_arr = (z == 0) ? ql : (z == 1) ? kl : vl;
        const float scale = (z == 0) ? QSCALE_LOG2 : 1.0f;

        #pragma unroll
        for (int m = 0; m < 2; m++) {
            int r = rbase + m * 16;
            if (z < 2) {
                int p0 = pos[r], p1 = pos[r + 8];
                const float* cr0 = cosc + (size_t)p0 * HALF;
                const float* sr0 = sinc + (size_t)p0 * HALF;
                const float* cr1 = cosc + (size_t)p1 * HALF;
                const float* sr1 = sinc + (size_t)p1 * HALF;
                #pragma unroll
                for (int nt = 0; nt < 8; nt++) {
                    const float* v = acc[m][nt];
                    int c  = cbase + nt * 8;
                    int dh = c & 63;
                    int hh = c >> 6;
                    float cc = cr0[dh >> 1], ssv = sr0[dh >> 1];
                    float re = (v[0] * cc - v[1] * ssv) * scale;
                    float ro = (v[0] * ssv + v[1] * cc) * scale;
                    split_store_pair(hi_arr, lo_arr,
                                     ((size_t)hh * SEQ + r) * DH + dh, re, ro);
                    cc = cr1[dh >> 1]; ssv = sr1[dh >> 1];
                    re = (v[2] * cc - v[3] * ssv) * scale;
                    ro = (v[2] * ssv + v[3] * cc) * scale;
                    split_store_pair(hi_arr, lo_arr,
                                     ((size_t)hh * SEQ + r + 8) * DH + dh, re, ro);
                }
            } else {
                #pragma unroll
                for (int nt = 0; nt < 8; nt++) {
                    const float* v = acc[m][nt];
                    int c  = cbase + nt * 8;
                    int dh = c & 63;
                    int hh = c >> 6;
                    split_store_pair(hi_arr, lo_arr,
                                     ((size_t)hh * SEQ + r) * DH + dh, v[0], v[1]);
                    split_store_pair(hi_arr, lo_arr,
                                     ((size_t)hh * SEQ + r + 8) * DH + dh, v[2], v[3]);
                }
            }
        }
    }
}

// ---------------------------------------------------------------------------
// Reduce the two split-K partials into the final output (deterministic).
// ---------------------------------------------------------------------------
__global__ __launch_bounds__(256)
void reduce_add_kernel(const float* __restrict__ p, float* __restrict__ out)
{
    int i = (blockIdx.x * 256 + threadIdx.x) * 4;
    float4 a = *(const float4*)(p + i);
    float4 b = *(const float4*)(p + SEQ * DMODEL + i);
    *(float4*)(out + i) = make_float4(a.x + b.x, a.y + b.y, a.z + b.z, a.w + b.w);
}

// ---------------------------------------------------------------------------
// Flash attention, split-bf16 mma, 64 q-rows/CTA, 3 CTAs/SM.  (R12 exact)
// ---------------------------------------------------------------------------
__global__ __launch_bounds__(128, 3)
void attn_mma(const bf16* __restrict__ Qh, const bf16* __restrict__ Ql,
              const bf16* __restrict__ Kh, const bf16* __restrict__ Kl,
              const bf16* __restrict__ Vh, const bf16* __restrict__ Vl,
              bf16* __restrict__ Oh, bf16* __restrict__ Ol,
              float* __restrict__ po, float* __restrict__ pm,
              float* __restrict__ pl)
{
    extern __shared__ __align__(128) uint8_t sm[];

    const int bx  = blockIdx.x;
    int h, qb, t0, t1, pslot;
    if (bx < NSPLIT_CTA) {
        int qi = bx / (NH * 2);        // 0..31, qb = 63 - qi (big first)
        int r  = bx % (NH * 2);
        h = r >> 1;
        int half = r & 1;
        qb = 63 - qi;
        int nt  = qb + 1;
        int ntA = (nt + 1) >> 1;
        t0 = half ? ntA : 0;
        t1 = half ? nt  : ntA;
        pslot = h * 64 + (qb - QB_SPLIT) * 2 + half;
    } else {
        int j = bx - NSPLIT_CTA;
        qb = QB_SPLIT - 1 - j / NH;    // 31..0 big first
        h = j % NH;
        t0 = 0;
        t1 = qb + 1;
        pslot = -1;
    }
    const int q0  = qb * 64;
    const int tid = threadIdx.x;
    const int wid = tid >> 5;
    const int lane = tid & 31;

    const size_t hoff = (size_t)h * SEQ * DH;
    const uint32_t smbase = (uint32_t)__cvta_generic_to_shared(sm);

    {
        const uint8_t* qsH = (const uint8_t*)(Qh + hoff + (size_t)q0 * DH);
        const uint8_t* qsL = (const uint8_t*)(Ql + hoff + (size_t)q0 * DH);
        for (int i = tid; i < 512; i += 128) {
            int row = i >> 3, ch = i & 7;
            uint32_t off = row * 128 + ((ch ^ (row & 7)) << 4);
            *(uint4*)(sm + off)        = *(const uint4*)(qsH + row * 128 + ch * 16);
            *(uint4*)(sm + 8192 + off) = *(const uint4*)(qsL + row * 128 + ch * 16);
        }
    }
    __syncthreads();

    uint32_t qfh[4][4], qfl[4][4];
    {
        int row = wid * 16 + (lane & 15);
        int chs = lane >> 4;
        #pragma unroll
        for (int kt = 0; kt < 4; kt++) {
            int ch = 2 * kt + chs;
            uint32_t off = row * 128 + ((ch ^ (row & 7)) << 4);
            ldsm4(qfh[kt], smbase + off);
            ldsm4(qfl[kt], smbase + 8192 + off);
        }
    }
    __syncthreads();

    const uint8_t* kHp = (const uint8_t*)(Kh + hoff);
    const uint8_t* kLp = (const uint8_t*)(Kl + hoff);
    const uint8_t* vHp = (const uint8_t*)(Vh + hoff);
    const uint8_t* vLp = (const uint8_t*)(Vl + hoff);

    auto issue_tile = [&](int k0, int stage) {
        uint32_t sb = smbase + stage * 32768;
        #pragma unroll
        for (int i = tid; i < 512; i += 128) {
            int row = i >> 3, ch = i & 7;
            uint32_t off = row * 128 + ((ch ^ (row & 7)) << 4);
            size_t g = (size_t)(k0 + row) * 128 + ch * 16;
            cp16(sb + off,         kHp + g);
            cp16(sb +  8192 + off, kLp + g);
            cp16(sb + 16384 + off, vHp + g);
            cp16(sb + 24576 + off, vLp + g);
        }
    };

    float o[8][4];
    #pragma unroll
    for (int i = 0; i < 8; i++)
        #pragma unroll
        for (int j = 0; j < 4; j++) o[i][j] = 0.0f;
    float mr0 = -1e30f, mr1 = -1e30f, lr0 = 0.0f, lr1 = 0.0f;

    const int rmax = q0 + wid * 16 + 15;
    const int r0g  = q0 + wid * 16 + (lane >> 2);

    issue_tile(t0 * 64, t0 & 1);
    CP_COMMIT();

    for (int t = t0; t < t1; t++) {
        const int k0 = t * 64;

        if (t + 1 < t1) {
            issue_tile((t + 1) * 64, (t + 1) & 1);
            CP_COMMIT();
            CP_WAIT(1);
        } else {
            CP_WAIT(0);
        }
        __syncthreads();

        if (k0 <= rmax) {
            const uint32_t sb = smbase + (t & 1) * 32768;

            float s[8][4];
            #pragma unroll
            for (int nt = 0; nt < 8; nt++)
                #pragma unroll
                for (int j = 0; j < 4; j++) s[nt][j] = 0.0f;

            #pragma unroll
            for (int nt = 0; nt < 8; nt++) {
                uint32_t bh[8], bl[8];
                int row = nt * 8 + (lane & 7);
                {
                    int ch = lane >> 3;
                    uint32_t off = row * 128 + ((ch ^ (row & 7)) << 4);
                    ldsm4(bh,     sb + off);
                    ldsm4(bl,     sb + 8192 + off);
                    int ch2 = 4 + (lane >> 3);
                    uint32_t off2 = row * 128 + ((ch2 ^ (row & 7)) << 4);
                    ldsm4(bh + 4, sb + off2);
                    ldsm4(bl + 4, sb + 8192 + off2);
                }
                #pragma unroll
                for (int kt = 0; kt < 4; kt++) {
                    mma16816(s[nt], qfh[kt], bh + 2 * kt);
                    mma16816(s[nt], qfh[kt], bl + 2 * kt);
                    mma16816(s[nt], qfl[kt], bh + 2 * kt);
                }
            }

            if (k0 + 63 > q0 + wid * 16) {
                #pragma unroll
                for (int nt = 0; nt < 8; nt++) {
                    int c0 = k0 + nt * 8 + ((lane & 3) << 1);
                    if (c0     > r0g)     s[nt][0] = -1e30f;
                    if (c0 + 1 > r0g)     s[nt][1] = -1e30f;
                    if (c0     > r0g + 8) s[nt][2] = -1e30f;
                    if (c0 + 1 > r0g + 8) s[nt][3] = -1e30f;
                }
            }

            float mx0 = -1e30f, mx1 = -1e30f;
            #pragma unroll
            for (int nt = 0; nt < 8; nt++) {
                mx0 = fmaxf(mx0, fmaxf(s[nt][0], s[nt][1]));
                mx1 = fmaxf(mx1, fmaxf(s[nt][2], s[nt][3]));
            }
            mx0 = fmaxf(mx0, __shfl_xor_sync(0xffffffffu, mx0, 1));
            mx0 = fmaxf(mx0, __shfl_xor_sync(0xffffffffu, mx0, 2));
            mx1 = fmaxf(mx1, __shfl_xor_sync(0xffffffffu, mx1, 1));
            mx1 = fmaxf(mx1, __shfl_xor_sync(0xffffffffu, mx1, 2));

            float mn0 = fmaxf(mr0, mx0), mn1 = fmaxf(mr1, mx1);
            float c0 = ex2f(mr0 - mn0), c1 = ex2f(mr1 - mn1);
            mr0 = mn0; mr1 = mn1;

            float sum0 = 0.0f, sum1 = 0.0f;
            #pragma unroll
            for (int nt = 0; nt < 8; nt++) {
                s[nt][0] = ex2f(s[nt][0] - mn0);
                s[nt][1] = ex2f(s[nt][1] - mn0);
                s[nt][2] = ex2f(s[nt][2] - mn1);
                s[nt][3] = ex2f(s[nt][3] - mn1);
                sum0 += s[nt][0] + s[nt][1];
                sum1 += s[nt][2] + s[nt][3];
            }
            lr0 = lr0 * c0 + sum0;
            lr1 = lr1 * c1 + sum1;

            #pragma unroll
            for (int dt = 0; dt < 8; dt++) {
                o[dt][0] *= c0; o[dt][1] *= c0;
                o[dt][2] *= c1; o[dt][3] *= c1;
            }

            uint32_t pfh[4][4], pfl[4][4];
            #pragma unroll
            for (int kt = 0; kt < 4; kt++) {
                splitpack(s[2*kt][0],   s[2*kt][1],   pfh[kt][0], pfl[kt][0]);
                splitpack(s[2*kt][2],   s[2*kt][3],   pfh[kt][1], pfl[kt][1]);
                splitpack(s[2*kt+1][0], s[2*kt+1][1], pfh[kt][2], pfl[kt][2]);
                splitpack(s[2*kt+1][2], s[2*kt+1][3], pfh[kt][3], pfl[kt][3]);
            }

            #pragma unroll
            for (int kt = 0; kt < 4; kt++) {
                #pragma unroll
                for (int dq = 0; dq < 2; dq++) {
                    uint32_t vh4[2][4], vl4[2][4];
                    #pragma unroll
                    for (int d = 0; d < 2; d++) {
                        int dp = dq * 2 + d;
                        int vrow = kt * 16 + (lane & 15);
                        int ch = 2 * dp + (lane >> 4);
                        uint32_t off = vrow * 128 + ((ch ^ (vrow & 7)) << 4);
                        ldsm4t(vh4[d], sb + 16384 + off);
                        ldsm4t(vl4[d], sb + 24576 + off);
                    }
                    #pragma unroll
                    for (int d = 0; d < 2; d++) {
                        int dp = dq * 2 + d;
                        mma16816(o[2*dp],     pfh[kt], vh4[d]);
                        mma16816(o[2*dp + 1], pfh[kt], vh4[d] + 2);
                        mma16816(o[2*dp],     pfh[kt], vl4[d]);
                        mma16816(o[2*dp + 1], pfh[kt], vl4[d] + 2);
                        mma16816(o[2*dp],     pfl[kt], vh4[d]);
                        mma16816(o[2*dp + 1], pfl[kt], vh4[d] + 2);
                    }
                }
            }
        }
        __syncthreads();
    }

    // deferred cross-lane l reduction (c factors are row-uniform)
    lr0 += __shfl_xor_sync(0xffffffffu, lr0, 1);
    lr0 += __shfl_xor_sync(0xffffffffu, lr0, 2);
    lr1 += __shfl_xor_sync(0xffffffffu, lr1, 1);
    lr1 += __shfl_xor_sync(0xffffffffu, lr1, 2);

    if (pslot < 0) {
        float i0 = 1.0f / lr0, i1 = 1.0f / lr1;
        int cb = h * DH + ((lane & 3) << 1);
        #pragma unroll
        for (int dt = 0; dt < 8; dt++) {
            split_store_pair(Oh, Ol, (size_t)r0g * DMODEL + cb + dt * 8,
                             o[dt][0] * i0, o[dt][1] * i0);
            split_store_pair(Oh, Ol, (size_t)(r0g + 8) * DMODEL + cb + dt * 8,
                             o[dt][2] * i1, o[dt][3] * i1);
        }
    } else {
        // unnormalized partial: o, m, l (log2 domain)
        float* pob = po + (size_t)pslot * 4096;
        int rA = wid * 16 + (lane >> 2);
        int cb2 = (lane & 3) * 2;
        #pragma unroll
        for (int dt = 0; dt < 8; dt++) {
            *(float2*)&pob[rA * 64 + cb2 + dt * 8]       = make_float2(o[dt][0], o[dt][1]);
            *(float2*)&pob[(rA + 8) * 64 + cb2 + dt * 8] = make_float2(o[dt][2], o[dt][3]);
        }
        if ((lane & 3) == 0) {
            pm[pslot * 64 + rA]     = mr0;
            pl[pslot * 64 + rA]     = lr0;
            pm[pslot * 64 + rA + 8] = mr1;
            pl[pslot * 64 + rA + 8] = lr1;
        }
    }
}

// ---------------------------------------------------------------------------
// Merge split-KV partials: one warp per row.
// ---------------------------------------------------------------------------
__global__ __launch_bounds__(128)
void attn_merge(const float* __restrict__ po, const float* __restrict__ pm,
                const float* __restrict__ pl,
                bf16* __restrict__ Oh, bf16* __restrict__ Ol)
{
    int row  = blockIdx.x * 4 + (threadIdx.x >> 5);   // 0 .. 24575
    int lane = threadIdx.x & 31;
    int h    = row / ((64 - QB_SPLIT) * 64);
    int rr   = row % ((64 - QB_SPLIT) * 64);
    int qrel = rr >> 6;
    int r    = rr & 63;

    int slotA = h * 64 + qrel * 2;
    const float* poA = po + (size_t)slotA * 4096 + r * 64;
    const float* poB = poA + 4096;
    float mA = pm[slotA * 64 + r], mB = pm[(slotA + 1) * 64 + r];
    float lA = pl[slotA * 64 + r], lB = pl[(slotA + 1) * 64 + r];
    float M  = fmaxf(mA, mB);
    float cA = ex2f(mA - M), cB = ex2f(mB - M);
    float inv = 1.0f / (cA * lA + cB * lB);

    int srow = (QB_SPLIT + qrel) * 64 + r;
    int c    = lane * 2;
    float a = (cA * poA[c]     + cB * poB[c])     * inv;
    float b = (cA * poA[c + 1] + cB * poB[c + 1]) * inv;
    split_store_pair(Oh, Ol, (size_t)srow * DMODEL + h * DH + c, a, b);
}

// ---------------------------------------------------------------------------
// kernel_launch — graph-capturable, allocation-free.
// ---------------------------------------------------------------------------
extern "C" void kernel_launch(void* const* d_in, const int* in_sizes, int n_in,
                              void* d_out, int out_size)
{
    const float* x   = (const float*)d_in[0];
    const float* wq  = (const float*)d_in[1];
    const float* wk  = (const float*)d_in[2];
    const float* wv  = (const float*)d_in[3];
    const float* wo  = (const float*)d_in[4];
    const int*   pos = (const int*)d_in[5];
    float* out = (float*)d_out;

    bf16 *xh, *xl, *wh, *wl, *oh, *ol;
    bf16 *qh, *ql, *kh, *kl, *vh, *vl;
    float *cp, *sp, *pop, *pmp, *plp, *pcp;
    cudaGetSymbolAddress((void**)&xh, g_xh);
    cudaGetSymbolAddress((void**)&xl, g_xl);
    cudaGetSymbolAddress((void**)&wh, g_wh);
    cudaGetSymbolAddress((void**)&wl, g_wl);
    cudaGetSymbolAddress((void**)&oh, g_oh);
    cudaGetSymbolAddress((void**)&ol, g_ol);
    cudaGetSymbolAddress((void**)&qh, g_qh);
    cudaGetSymbolAddress((void**)&ql, g_ql);
    cudaGetSymbolAddress((void**)&kh, g_kh);
    cudaGetSymbolAddress((void**)&kl, g_kl);
    cudaGetSymbolAddress((void**)&vh, g_vh);
    cudaGetSymbolAddress((void**)&vl, g_vl);
    cudaGetSymbolAddress((void**)&cp, g_cos);
    cudaGetSymbolAddress((void**)&sp, g_sin);
    cudaGetSymbolAddress((void**)&pop, g_po);
    cudaGetSymbolAddress((void**)&pmp, g_pm);
    cudaGetSymbolAddress((void**)&plp, g_pl);
    cudaGetSymbolAddress((void**)&pcp, g_pc);

    const int gemm_smem = 3 * 32768;   // 98304
    const int attn_smem = 65536;
    cudaFuncSetAttribute(gemm_bf<1>, cudaFuncAttributeMaxDynamicSharedMemorySize, gemm_smem);
    cudaFuncSetAttribute(gemm_bf<2>, cudaFuncAttributeMaxDynamicSharedMemorySize, gemm_smem);
    cudaFuncSetAttribute(attn_mma,   cudaFuncAttributeMaxDynamicSharedMemorySize, attn_smem);

    // 1. hi/lo split of x + weights, and RoPE cache (fused launch)
    convert_split_kernel<<<dim3((SEQ * DMODEL / 8 + 255) / 256, 6), 256>>>(
        x, wq, wk, wv, wo, xh, xl, wh, wl, cp, sp);

    // 2. QKV projections (Q scaled by 0.125*log2e for exp2-domain softmax)
    dim3 gq(DMODEL / 128, SEQ / 128, 3);
    gemm_bf<1><<<gq, 256, gemm_smem>>>(xh, xl, wh, wl, nullptr,
                                       qh, ql, kh, kl, vh, vl, pos, cp, sp);

    // 3. Causal flash attention: unified grid, big KV-halves first
    attn_mma<<<NSPLIT_CTA + NNORM_CTA, 128, attn_smem>>>(
        qh, ql, kh, kl, vh, vl, oh, ol, pop, pmp, plp);

    // 3b. Merge split-KV partials
    attn_merge<<<(NH * (64 - QB_SPLIT) * 64) / 4, 128>>>(pop, pmp, plp, oh, ol);

    // 4. Output projection, split-K 2-way into partials
    dim3 gg(DMODEL / 128, SEQ / 128, 2);
    gemm_bf<2><<<gg, 256, gemm_smem>>>(oh, ol, wh + (size_t)3 * WELEM, wl + (size_t)3 * WELEM,
                                       pcp, nullptr, nullptr, nullptr, nullptr,
                                       nullptr, nullptr, nullptr, nullptr, nullptr);

    // 4b. Reduce partials into the final output
    reduce_add_kernel<<<SEQ * DMODEL / 4 / 256, 256>>>(pcp, out);
}

// round 16
// speedup vs baseline: 1.5017x; 1.5017x over previous
#include <cuda_runtime.h>
#include <cuda_bf16.h>
#include <math.h>
#include <stdint.h>

using bf16 = __nv_bfloat16;

constexpr int SEQ    = 4096;
constexpr int DMODEL = 768;
constexpr int NH     = 12;
constexpr int DH     = 64;
constexpr int HALF   = DH / 2;   // 32
constexpr int WELEM  = DMODEL * DMODEL;

// Q pre-scale: (1/sqrt(64)) * log2(e)  -> softmax computed in exp2 domain
constexpr float QSCALE_LOG2 = 0.125f * 1.44269504088896340736f;

// attention work split: qb in [32,63] handled by 2 CTAs (KV halves) + merge
constexpr int QB_SPLIT   = 32;
constexpr int NSPLIT_CTA = (64 - QB_SPLIT) * NH * 2;   // 768
constexpr int NNORM_CTA  = QB_SPLIT * NH;              // 384

// Scratch (device globals; no runtime allocation allowed)
__device__ bf16  g_xh[SEQ * DMODEL];
__device__ bf16  g_xl[SEQ * DMODEL];
__device__ bf16  g_wh[4 * WELEM];
__device__ bf16  g_wl[4 * WELEM];
__device__ bf16  g_oh[SEQ * DMODEL];
__device__ bf16  g_ol[SEQ * DMODEL];
__device__ bf16  g_qh[NH * SEQ * DH];
__device__ bf16  g_ql[NH * SEQ * DH];
__device__ bf16  g_kh[NH * SEQ * DH];
__device__ bf16  g_kl[NH * SEQ * DH];
__device__ bf16  g_vh[NH * SEQ * DH];
__device__ bf16  g_vl[NH * SEQ * DH];
__device__ float g_cos[SEQ * HALF];
__device__ float g_sin[SEQ * HALF];
// split-KV partials: 768 slots x 64 rows x 64 cols + m/l per row
__device__ float g_po[NSPLIT_CTA * 64 * 64];
__device__ float g_pm[NSPLIT_CTA * 64];
__device__ float g_pl[NSPLIT_CTA * 64];

// ---------------------------------------------------------------------------
// bf16 split helpers
// ---------------------------------------------------------------------------
__device__ __forceinline__ void split_store_pair(bf16* __restrict__ hi_arr,
                                                 bf16* __restrict__ lo_arr,
                                                 size_t idx, float a, float b)
{
    __nv_bfloat162 h = __floats2bfloat162_rn(a, b);
    float ha = __bfloat162float(h.x);
    float hb = __bfloat162float(h.y);
    __nv_bfloat162 l = __floats2bfloat162_rn(a - ha, b - hb);
    *reinterpret_cast<__nv_bfloat162*>(hi_arr + idx) = h;
    *reinterpret_cast<__nv_bfloat162*>(lo_arr + idx) = l;
}

__device__ __forceinline__ void splitpack(float a, float b,
                                          uint32_t& hi, uint32_t& lo)
{
    __nv_bfloat162 h = __floats2bfloat162_rn(a, b);
    float ha = __bfloat162float(h.x);
    float hb = __bfloat162float(h.y);
    __nv_bfloat162 l = __floats2bfloat162_rn(a - ha, b - hb);
    hi = *reinterpret_cast<uint32_t*>(&h);
    lo = *reinterpret_cast<uint32_t*>(&l);
}

__device__ __forceinline__ void cvt8_split(const float4& p0, const float4& p1,
                                           uint4& hi, uint4& lo)
{
    uint32_t h0, l0, h1, l1, h2, l2, h3, l3;
    splitpack(p0.x, p0.y, h0, l0);
    splitpack(p0.z, p0.w, h1, l1);
    splitpack(p1.x, p1.y, h2, l2);
    splitpack(p1.z, p1.w, h3, l3);
    hi = make_uint4(h0, h1, h2, h3);
    lo = make_uint4(l0, l1, l2, l3);
}

__device__ __forceinline__ float ex2f(float x)
{
    float y;
    asm("ex2.approx.ftz.f32 %0, %1;" : "=f"(y) : "f"(x));
    return y;
}

// ---------------------------------------------------------------------------
// One-time fp32 -> bf16 hi/lo conversion of x and the 4 weights + RoPE cache.
// grid.y: 0=x, 1..4=weights, 5=rope cache.
// ---------------------------------------------------------------------------
__global__ __launch_bounds__(256)
void convert_split_kernel(const float* __restrict__ x,
                          const float* __restrict__ wq, const float* __restrict__ wk,
                          const float* __restrict__ wv, const float* __restrict__ wo,
                          bf16* __restrict__ xh, bf16* __restrict__ xl,
                          bf16* __restrict__ wh, bf16* __restrict__ wl,
                          float* __restrict__ cc, float* __restrict__ ss)
{
    int y = blockIdx.y;
    if (y == 5) {
        int i = blockIdx.x * 256 + threadIdx.x;
        if (i >= SEQ * HALF) return;
        int p = i >> 5;
        int k = i & 31;
        float expo = -2.0f * (float)k / (float)DH;
        float invf = powf(10000.0f, expo);
        float ang  = (float)p * invf;
        cc[i] = cosf(ang);
        ss[i] = sinf(ang);
        return;
    }
    const float* src;
    bf16 *dh, *dl;
    int n;
    if (y == 0) { src = x;  dh = xh; dl = xl; n = SEQ * DMODEL; }
    else {
        src = (y == 1) ? wq : (y == 2) ? wk : (y == 3) ? wv : wo;
        dh = wh + (size_t)(y - 1) * WELEM;
        dl = wl + (size_t)(y - 1) * WELEM;
        n = WELEM;
    }
    int i = (blockIdx.x * 256 + threadIdx.x) * 8;
    if (i >= n) return;
    float4 a = *(const float4*)(src + i);
    float4 b = *(const float4*)(src + i + 4);
    uint4 hi, lo;
    cvt8_split(a, b, hi, lo);
    *(uint4*)(dh + i) = hi;
    *(uint4*)(dl + i) = lo;
}

// ---------------------------------------------------------------------------
// mma / ldmatrix / cp.async wrappers
// ---------------------------------------------------------------------------
__device__ __forceinline__ void ldsm4(uint32_t* r, uint32_t addr)
{
    asm volatile("ldmatrix.sync.aligned.m8n8.x4.shared.b16 {%0,%1,%2,%3}, [%4];"
        : "=r"(r[0]), "=r"(r[1]), "=r"(r[2]), "=r"(r[3]) : "r"(addr));
}
__device__ __forceinline__ void ldsm4t(uint32_t* r, uint32_t addr)
{
    asm volatile("ldmatrix.sync.aligned.m8n8.x4.trans.shared.b16 {%0,%1,%2,%3}, [%4];"
        : "=r"(r[0]), "=r"(r[1]), "=r"(r[2]), "=r"(r[3]) : "r"(addr));
}
__device__ __forceinline__ void mma16816(float* d, const uint32_t* a, const uint32_t* b)
{
    asm volatile(
        "mma.sync.aligned.m16n8k16.row.col.f32.bf16.bf16.f32 "
        "{%0,%1,%2,%3}, {%4,%5,%6,%7}, {%8,%9}, {%0,%1,%2,%3};"
        : "+f"(d[0]), "+f"(d[1]), "+f"(d[2]), "+f"(d[3])
        : "r"(a[0]), "r"(a[1]), "r"(a[2]), "r"(a[3]), "r"(b[0]), "r"(b[1]));
}
__device__ __forceinline__ void cp16(uint32_t dst, const void* src)
{
    asm volatile("cp.async.cg.shared.global [%0], [%1], 16;"
        :: "r"(dst), "l"(src));
}
#define CP_COMMIT() asm volatile("cp.async.commit_group;")
#define CP_WAIT(n)  asm volatile("cp.async.wait_group %0;" :: "n"(n))

// ---------------------------------------------------------------------------
// Split-bf16 NT GEMM on pre-split inputs.
// MODE 0: fp32 store. MODE 1: QKV by blockIdx.z; RoPE for z<2; split scatter.
// ---------------------------------------------------------------------------
template<int MODE>
__global__ __launch_bounds__(256, 2)
void gemm_bf(const bf16* __restrict__ Agh, const bf16* __restrict__ Agl,
             const bf16* __restrict__ Wgh, const bf16* __restrict__ Wgl,
             float* __restrict__ Cout,
             bf16* __restrict__ qh, bf16* __restrict__ ql,
             bf16* __restrict__ kh, bf16* __restrict__ kl,
             bf16* __restrict__ vh, bf16* __restrict__ vl,
             const int* __restrict__ pos,
             const float* __restrict__ cosc, const float* __restrict__ sinc)
{
    constexpr int KD  = 768;
    constexpr int NCH = KD / 32;  // 24
    extern __shared__ __align__(128) uint8_t sm[];
    const uint32_t smb = (uint32_t)__cvta_generic_to_shared(sm);

    const int tid  = threadIdx.x;
    const int wid  = tid >> 5;
    const int lane = tid & 31;
    const int z    = (MODE == 1) ? blockIdx.z : 0;
    const bf16* Bgh = Wgh + (size_t)z * WELEM;
    const bf16* Bgl = Wgl + (size_t)z * WELEM;
    const int m0   = blockIdx.y * 128;
    const int n0   = blockIdx.x * 128;
    const int wm   = wid >> 1;
    const int wn   = wid & 1;

    float acc[2][8][4];
    #pragma unroll
    for (int m = 0; m < 2; m++)
        #pragma unroll
        for (int n = 0; n < 8; n++)
            #pragma unroll
            for (int j = 0; j < 4; j++) acc[m][n][j] = 0.0f;

    auto cp_chunk = [&](int c, int s) {
        uint32_t base = smb + s * 32768;
        int kb = c * 32;
        #pragma unroll
        for (int it = 0; it < 2; it++) {
            int i   = it * 256 + tid;
            int row = i >> 2, o = i & 3;
            uint32_t off = (uint32_t)(row * 64 + ((o ^ (row & 3)) << 4));
            size_t ga = (size_t)(m0 + row) * KD + kb + o * 8;
            size_t gb = (size_t)(n0 + row) * KD + kb + o * 8;
            cp16(base + off,         Agh + ga);
            cp16(base +  8192 + off, Agl + ga);
            cp16(base + 16384 + off, Bgh + gb);
            cp16(base + 24576 + off, Bgl + gb);
        }
    };

    cp_chunk(0, 0); CP_COMMIT();
    cp_chunk(1, 1); CP_COMMIT();

    for (int c = 0; c < NCH; c++) {
        if (c < NCH - 1) { CP_WAIT(1); } else { CP_WAIT(0); }
        __syncthreads();
        if (c + 2 < NCH) { cp_chunk(c + 2, (c + 2) % 3); CP_COMMIT(); }

        const uint32_t sb = smb + (c % 3) * 32768;
        #pragma unroll
        for (int kt = 0; kt < 2; kt++) {
            uint32_t ah[2][4], al[2][4];
            #pragma unroll
            for (int m = 0; m < 2; m++) {
                int row = wm * 32 + m * 16 + (lane & 15);
                int ch  = kt * 2 + (lane >> 4);
                uint32_t off = (uint32_t)(row * 64 + ((ch ^ (row & 3)) << 4));
                ldsm4(ah[m], sb + off);
                ldsm4(al[m], sb + 8192 + off);
            }
            uint32_t bh4[4][4], bl4[4][4];
            #pragma unroll
            for (int np = 0; np < 4; np++) {
                int row = wn * 64 + np * 16 + (lane & 7) + ((lane >> 4) << 3);
                int ch  = kt * 2 + ((lane >> 3) & 1);
                uint32_t off = (uint32_t)(row * 64 + ((ch ^ (row & 3)) << 4));
                ldsm4(bh4[np], sb + 16384 + off);
                ldsm4(bl4[np], sb + 24576 + off);
            }
            #pragma unroll
            for (int m = 0; m < 2; m++)
                #pragma unroll
                for (int np = 0; np < 4; np++) {
                    mma16816(acc[m][2*np],     ah[m], bh4[np]);
                    mma16816(acc[m][2*np + 1], ah[m], bh4[np] + 2);
                }
            #pragma unroll
            for (int m = 0; m < 2; m++)
                #pragma unroll
                for (int np = 0; np < 4; np++) {
                    mma16816(acc[m][2*np],     ah[m], bl4[np]);
                    mma16816(acc[m][2*np + 1], ah[m], bl4[np] + 2);
                }
            #pragma unroll
            for (int m = 0; m < 2; m++)
                #pragma unroll
                for (int np = 0; np < 4; np++) {
                    mma16816(acc[m][2*np],     al[m], bh4[np]);
                    mma16816(acc[m][2*np + 1], al[m], bh4[np] + 2);
                }
        }
    }

    // ---- epilogue ----
    const int rbase = m0 + wm * 32 + (lane >> 2);
    const int cbase = n0 + wn * 64 + (lane & 3) * 2;

    if (MODE == 0) {
        #pragma unroll
        for (int m = 0; m < 2; m++)
            #pragma unroll
            for (int nt = 0; nt < 8; nt++) {
                const float* v = acc[m][nt];
                int r = rbase + m * 16;
                int c = cbase + nt * 8;
                *(float2*)&Cout[(size_t)r * DMODEL + c]       = make_float2(v[0], v[1]);
                *(float2*)&Cout[(size_t)(r + 8) * DMODEL + c] = make_float2(v[2], v[3]);
            }
    } else {
        bf16* hi_arr = (z == 0) ? qh : (z == 1) ? kh : vh;
        bf16* lo_arr = (z == 0) ? ql : (z == 1) ? kl : vl;
        const float scale = (z == 0) ? QSCALE_LOG2 : 1.0f;

        #pragma unroll
        for (int m = 0; m < 2; m++) {
            int r = rbase + m * 16;
            if (z < 2) {
                int p0 = pos[r], p1 = pos[r + 8];
                const float* cr0 = cosc + (size_t)p0 * HALF;
                const float* sr0 = sinc + (size_t)p0 * HALF;
                const float* cr1 = cosc + (size_t)p1 * HALF;
                const float* sr1 = sinc + (size_t)p1 * HALF;
                #pragma unroll
                for (int nt = 0; nt < 8; nt++) {
                    const float* v = acc[m][nt];
                    int c  = cbase + nt * 8;
                    int dh = c & 63;
                    int hh = c >> 6;
                    float cc = cr0[dh >> 1], ssv = sr0[dh >> 1];
                    float re = (v[0] * cc - v[1] * ssv) * scale;
                    float ro = (v[0] * ssv + v[1] * cc) * scale;
                    split_store_pair(hi_arr, lo_arr,
                                     ((size_t)hh * SEQ + r) * DH + dh, re, ro);
                    cc = cr1[dh >> 1]; ssv = sr1[dh >> 1];
                    re = (v[2] * cc - v[3] * ssv) * scale;
                    ro = (v[2] * ssv + v[3] * cc) * scale;
                    split_store_pair(hi_arr, lo_arr,
                                     ((size_t)hh * SEQ + r + 8) * DH + dh, re, ro);
                }
            } else {
                #pragma unroll
                for (int nt = 0; nt < 8; nt++) {
                    const float* v = acc[m][nt];
                    int c  = cbase + nt * 8;
                    int dh = c & 63;
                    int hh = c >> 6;
                    split_store_pair(hi_arr, lo_arr,
                                     ((size_t)hh * SEQ + r) * DH + dh, v[0], v[1]);
                    split_store_pair(hi_arr, lo_arr,
                                     ((size_t)hh * SEQ + r + 8) * DH + dh, v[2], v[3]);
                }
            }
        }
    }
}

// ---------------------------------------------------------------------------
// Flash attention, split-bf16 mma, 64 q-rows/CTA, 3 CTAs/SM.
// Unified grid: bx < NSPLIT_CTA -> KV-half of a big q-block (partial output);
// else -> full causal scan for qb < QB_SPLIT (direct Oh/Ol store).
// Decode is big-work-first so wave 1 gets the critical path.
// ---------------------------------------------------------------------------
__global__ __launch_bounds__(128, 3)
void attn_mma(const bf16* __restrict__ Qh, const bf16* __restrict__ Ql,
              const bf16* __restrict__ Kh, const bf16* __restrict__ Kl,
              const bf16* __restrict__ Vh, const bf16* __restrict__ Vl,
              bf16* __restrict__ Oh, bf16* __restrict__ Ol,
              float* __restrict__ po, float* __restrict__ pm,
              float* __restrict__ pl)
{
    extern __shared__ __align__(128) uint8_t sm[];

    const int bx  = blockIdx.x;
    int h, qb, t0, t1, pslot;
    if (bx < NSPLIT_CTA) {
        int qi = bx / (NH * 2);        // 0..31, qb = 63 - qi (big first)
        int r  = bx % (NH * 2);
        h = r >> 1;
        int half = r & 1;
        qb = 63 - qi;
        int nt  = qb + 1;
        int ntA = (nt + 1) >> 1;
        t0 = half ? ntA : 0;
        t1 = half ? nt  : ntA;
        pslot = h * 64 + (qb - QB_SPLIT) * 2 + half;
    } else {
        int j = bx - NSPLIT_CTA;
        qb = QB_SPLIT - 1 - j / NH;    // 31..0 big first
        h = j % NH;
        t0 = 0;
        t1 = qb + 1;
        pslot = -1;
    }
    const int q0  = qb * 64;
    const int tid = threadIdx.x;
    const int wid = tid >> 5;
    const int lane = tid & 31;

    const size_t hoff = (size_t)h * SEQ * DH;
    const uint32_t smbase = (uint32_t)__cvta_generic_to_shared(sm);

    {
        const uint8_t* qsH = (const uint8_t*)(Qh + hoff + (size_t)q0 * DH);
        const uint8_t* qsL = (const uint8_t*)(Ql + hoff + (size_t)q0 * DH);
        for (int i = tid; i < 512; i += 128) {
            int row = i >> 3, ch = i & 7;
            uint32_t off = row * 128 + ((ch ^ (row & 7)) << 4);
            *(uint4*)(sm + off)        = *(const uint4*)(qsH + row * 128 + ch * 16);
            *(uint4*)(sm + 8192 + off) = *(const uint4*)(qsL + row * 128 + ch * 16);
        }
    }
    __syncthreads();

    uint32_t qfh[4][4], qfl[4][4];
    {
        int row = wid * 16 + (lane & 15);
        int chs = lane >> 4;
        #pragma unroll
        for (int kt = 0; kt < 4; kt++) {
            int ch = 2 * kt + chs;
            uint32_t off = row * 128 + ((ch ^ (row & 7)) << 4);
            ldsm4(qfh[kt], smbase + off);
            ldsm4(qfl[kt], smbase + 8192 + off);
        }
    }
    __syncthreads();

    const uint8_t* kHp = (const uint8_t*)(Kh + hoff);
    const uint8_t* kLp = (const uint8_t*)(Kl + hoff);
    const uint8_t* vHp = (const uint8_t*)(Vh + hoff);
    const uint8_t* vLp = (const uint8_t*)(Vl + hoff);

    auto issue_tile = [&](int k0, int stage) {
        uint32_t sb = smbase + stage * 32768;
        #pragma unroll
        for (int i = tid; i < 512; i += 128) {
            int row = i >> 3, ch = i & 7;
            uint32_t off = row * 128 + ((ch ^ (row & 7)) << 4);
            size_t g = (size_t)(k0 + row) * 128 + ch * 16;
            cp16(sb + off,         kHp + g);
            cp16(sb +  8192 + off, kLp + g);
            cp16(sb + 16384 + off, vHp + g);
            cp16(sb + 24576 + off, vLp + g);
        }
    };

    float o[8][4];
    #pragma unroll
    for (int i = 0; i < 8; i++)
        #pragma unroll
        for (int j = 0; j < 4; j++) o[i][j] = 0.0f;
    float mr0 = -1e30f, mr1 = -1e30f, lr0 = 0.0f, lr1 = 0.0f;

    const int rmax = q0 + wid * 16 + 15;
    const int r0g  = q0 + wid * 16 + (lane >> 2);

    issue_tile(t0 * 64, t0 & 1);
    CP_COMMIT();

    for (int t = t0; t < t1; t++) {
        const int k0 = t * 64;

        if (t + 1 < t1) {
            issue_tile((t + 1) * 64, (t + 1) & 1);
            CP_COMMIT();
            CP_WAIT(1);
        } else {
            CP_WAIT(0);
        }
        __syncthreads();

        if (k0 <= rmax) {
            const uint32_t sb = smbase + (t & 1) * 32768;

            float s[8][4];
            #pragma unroll
            for (int nt = 0; nt < 8; nt++)
                #pragma unroll
                for (int j = 0; j < 4; j++) s[nt][j] = 0.0f;

            #pragma unroll
            for (int nt = 0; nt < 8; nt++) {
                uint32_t bh[8], bl[8];
                int row = nt * 8 + (lane & 7);
                {
                    int ch = lane >> 3;
                    uint32_t off = row * 128 + ((ch ^ (row & 7)) << 4);
                    ldsm4(bh,     sb + off);
                    ldsm4(bl,     sb + 8192 + off);
                    int ch2 = 4 + (lane >> 3);
                    uint32_t off2 = row * 128 + ((ch2 ^ (row & 7)) << 4);
                    ldsm4(bh + 4, sb + off2);
                    ldsm4(bl + 4, sb + 8192 + off2);
                }
                #pragma unroll
                for (int kt = 0; kt < 4; kt++) {
                    mma16816(s[nt], qfh[kt], bh + 2 * kt);
                    mma16816(s[nt], qfh[kt], bl + 2 * kt);
                    mma16816(s[nt], qfl[kt], bh + 2 * kt);
                }
            }

            if (k0 + 63 > q0 + wid * 16) {
                #pragma unroll
                for (int nt = 0; nt < 8; nt++) {
                    int c0 = k0 + nt * 8 + ((lane & 3) << 1);
                    if (c0     > r0g)     s[nt][0] = -1e30f;
                    if (c0 + 1 > r0g)     s[nt][1] = -1e30f;
                    if (c0     > r0g + 8) s[nt][2] = -1e30f;
                    if (c0 + 1 > r0g + 8) s[nt][3] = -1e30f;
                }
            }

            float mx0 = -1e30f, mx1 = -1e30f;
            #pragma unroll
            for (int nt = 0; nt < 8; nt++) {
                mx0 = fmaxf(mx0, fmaxf(s[nt][0], s[nt][1]));
                mx1 = fmaxf(mx1, fmaxf(s[nt][2], s[nt][3]));
            }
            mx0 = fmaxf(mx0, __shfl_xor_sync(0xffffffffu, mx0, 1));
            mx0 = fmaxf(mx0, __shfl_xor_sync(0xffffffffu, mx0, 2));
            mx1 = fmaxf(mx1, __shfl_xor_sync(0xffffffffu, mx1, 1));
            mx1 = fmaxf(mx1, __shfl_xor_sync(0xffffffffu, mx1, 2));

            float mn0 = fmaxf(mr0, mx0), mn1 = fmaxf(mr1, mx1);
            float c0 = ex2f(mr0 - mn0), c1 = ex2f(mr1 - mn1);
            mr0 = mn0; mr1 = mn1;

            float sum0 = 0.0f, sum1 = 0.0f;
            #pragma unroll
            for (int nt = 0; nt < 8; nt++) {
                s[nt][0] = ex2f(s[nt][0] - mn0);
                s[nt][1] = ex2f(s[nt][1] - mn0);
                s[nt][2] = ex2f(s[nt][2] - mn1);
                s[nt][3] = ex2f(s[nt][3] - mn1);
                sum0 += s[nt][0] + s[nt][1];
                sum1 += s[nt][2] + s[nt][3];
            }
            lr0 = lr0 * c0 + sum0;
            lr1 = lr1 * c1 + sum1;

            #pragma unroll
            for (int dt = 0; dt < 8; dt++) {
                o[dt][0] *= c0; o[dt][1] *= c0;
                o[dt][2] *= c1; o[dt][3] *= c1;
            }

            uint32_t pfh[4][4], pfl[4][4];
            #pragma unroll
            for (int kt = 0; kt < 4; kt++) {
                splitpack(s[2*kt][0],   s[2*kt][1],   pfh[kt][0], pfl[kt][0]);
                splitpack(s[2*kt][2],   s[2*kt][3],   pfh[kt][1], pfl[kt][1]);
                splitpack(s[2*kt+1][0], s[2*kt+1][1], pfh[kt][2], pfl[kt][2]);
                splitpack(s[2*kt+1][2], s[2*kt+1][3], pfh[kt][3], pfl[kt][3]);
            }

            #pragma unroll
            for (int kt = 0; kt < 4; kt++) {
                #pragma unroll
                for (int dq = 0; dq < 2; dq++) {
                    uint32_t vh4[2][4], vl4[2][4];
                    #pragma unroll
                    for (int d = 0; d < 2; d++) {
                        int dp = dq * 2 + d;
                        int vrow = kt * 16 + (lane & 15);
                        int ch = 2 * dp + (lane >> 4);
                        uint32_t off = vrow * 128 + ((ch ^ (vrow & 7)) << 4);
                        ldsm4t(vh4[d], sb + 16384 + off);
                        ldsm4t(vl4[d], sb + 24576 + off);
                    }
                    #pragma unroll
                    for (int d = 0; d < 2; d++) {
                        int dp = dq * 2 + d;
                        mma16816(o[2*dp],     pfh[kt], vh4[d]);
                        mma16816(o[2*dp + 1], pfh[kt], vh4[d] + 2);
                        mma16816(o[2*dp],     pfh[kt], vl4[d]);
                        mma16816(o[2*dp + 1], pfh[kt], vl4[d] + 2);
                        mma16816(o[2*dp],     pfl[kt], vh4[d]);
                        mma16816(o[2*dp + 1], pfl[kt], vh4[d] + 2);
                    }
                }
            }
        }
        __syncthreads();
    }

    // deferred cross-lane l reduction (c factors are row-uniform)
    lr0 += __shfl_xor_sync(0xffffffffu, lr0, 1);
    lr0 += __shfl_xor_sync(0xffffffffu, lr0, 2);
    lr1 += __shfl_xor_sync(0xffffffffu, lr1, 1);
    lr1 += __shfl_xor_sync(0xffffffffu, lr1, 2);

    if (pslot < 0) {
        float i0 = 1.0f / lr0, i1 = 1.0f / lr1;
        int cb = h * DH + ((lane & 3) << 1);
        #pragma unroll
        for (int dt = 0; dt < 8; dt++) {
            split_store_pair(Oh, Ol, (size_t)r0g * DMODEL + cb + dt * 8,
                             o[dt][0] * i0, o[dt][1] * i0);
            split_store_pair(Oh, Ol, (size_t)(r0g + 8) * DMODEL + cb + dt * 8,
                             o[dt][2] * i1, o[dt][3] * i1);
        }
    } else {
        // unnormalized partial: o, m, l (log2 domain)
        float* pob = po + (size_t)pslot * 4096;
        int rA = wid * 16 + (lane >> 2);
        int cb2 = (lane & 3) * 2;
        #pragma unroll
        for (int dt = 0; dt < 8; dt++) {
            *(float2*)&pob[rA * 64 + cb2 + dt * 8]       = make_float2(o[dt][0], o[dt][1]);
            *(float2*)&pob[(rA + 8) * 64 + cb2 + dt * 8] = make_float2(o[dt][2], o[dt][3]);
        }
        if ((lane & 3) == 0) {
            pm[pslot * 64 + rA]     = mr0;
            pl[pslot * 64 + rA]     = lr0;
            pm[pslot * 64 + rA + 8] = mr1;
            pl[pslot * 64 + rA + 8] = lr1;
        }
    }
}

// ---------------------------------------------------------------------------
// Merge split-KV partials: one warp per row.
// ---------------------------------------------------------------------------
__global__ __launch_bounds__(128)
void attn_merge(const float* __restrict__ po, const float* __restrict__ pm,
                const float* __restrict__ pl,
                bf16* __restrict__ Oh, bf16* __restrict__ Ol)
{
    int row  = blockIdx.x * 4 + (threadIdx.x >> 5);   // 0 .. 24575
    int lane = threadIdx.x & 31;
    int h    = row / ((64 - QB_SPLIT) * 64);
    int rr   = row % ((64 - QB_SPLIT) * 64);
    int qrel = rr >> 6;
    int r    = rr & 63;

    int slotA = h * 64 + qrel * 2;
    const float* poA = po + (size_t)slotA * 4096 + r * 64;
    const float* poB = poA + 4096;
    float mA = pm[slotA * 64 + r], mB = pm[(slotA + 1) * 64 + r];
    float lA = pl[slotA * 64 + r], lB = pl[(slotA + 1) * 64 + r];
    float M  = fmaxf(mA, mB);
    float cA = ex2f(mA - M), cB = ex2f(mB - M);
    float inv = 1.0f / (cA * lA + cB * lB);

    int srow = (QB_SPLIT + qrel) * 64 + r;
    int c    = lane * 2;
    float a = (cA * poA[c]     + cB * poB[c])     * inv;
    float b = (cA * poA[c + 1] + cB * poB[c + 1]) * inv;
    split_store_pair(Oh, Ol, (size_t)srow * DMODEL + h * DH + c, a, b);
}

// ---------------------------------------------------------------------------
// kernel_launch — graph-capturable, allocation-free.
// ---------------------------------------------------------------------------
extern "C" void kernel_launch(void* const* d_in, const int* in_sizes, int n_in,
                              void* d_out, int out_size)
{
    const float* x   = (const float*)d_in[0];
    const float* wq  = (const float*)d_in[1];
    const float* wk  = (const float*)d_in[2];
    const float* wv  = (const float*)d_in[3];
    const float* wo  = (const float*)d_in[4];
    const int*   pos = (const int*)d_in[5];
    float* out = (float*)d_out;

    bf16 *xh, *xl, *wh, *wl, *oh, *ol;
    bf16 *qh, *ql, *kh, *kl, *vh, *vl;
    float *cp, *sp, *pop, *pmp, *plp;
    cudaGetSymbolAddress((void**)&xh, g_xh);
    cudaGetSymbolAddress((void**)&xl, g_xl);
    cudaGetSymbolAddress((void**)&wh, g_wh);
    cudaGetSymbolAddress((void**)&wl, g_wl);
    cudaGetSymbolAddress((void**)&oh, g_oh);
    cudaGetSymbolAddress((void**)&ol, g_ol);
    cudaGetSymbolAddress((void**)&qh, g_qh);
    cudaGetSymbolAddress((void**)&ql, g_ql);
    cudaGetSymbolAddress((void**)&kh, g_kh);
    cudaGetSymbolAddress((void**)&kl, g_kl);
    cudaGetSymbolAddress((void**)&vh, g_vh);
    cudaGetSymbolAddress((void**)&vl, g_vl);
    cudaGetSymbolAddress((void**)&cp, g_cos);
    cudaGetSymbolAddress((void**)&sp, g_sin);
    cudaGetSymbolAddress((void**)&pop, g_po);
    cudaGetSymbolAddress((void**)&pmp, g_pm);
    cudaGetSymbolAddress((void**)&plp, g_pl);

    const int gemm_smem = 3 * 32768;   // 98304
    const int attn_smem = 65536;
    cudaFuncSetAttribute(gemm_bf<0>, cudaFuncAttributeMaxDynamicSharedMemorySize, gemm_smem);
    cudaFuncSetAttribute(gemm_bf<1>, cudaFuncAttributeMaxDynamicSharedMemorySize, gemm_smem);
    cudaFuncSetAttribute(attn_mma,   cudaFuncAttributeMaxDynamicSharedMemorySize, attn_smem);

    // 1. hi/lo split of x + weights, and RoPE cache (fused launch)
    convert_split_kernel<<<dim3((SEQ * DMODEL / 8 + 255) / 256, 6), 256>>>(
        x, wq, wk, wv, wo, xh, xl, wh, wl, cp, sp);

    // 2. QKV projections (Q scaled by 0.125*log2e for exp2-domain softmax)
    dim3 gq(DMODEL / 128, SEQ / 128, 3);
    gemm_bf<1><<<gq, 256, gemm_smem>>>(xh, xl, wh, wl, nullptr,
                                       qh, ql, kh, kl, vh, vl, pos, cp, sp);

    // 3. Causal flash attention: unified grid, big KV-halves first
    attn_mma<<<NSPLIT_CTA + NNORM_CTA, 128, attn_smem>>>(
        qh, ql, kh, kl, vh, vl, oh, ol, pop, pmp, plp);

    // 3b. Merge split-KV partials
    attn_merge<<<(NH * (64 - QB_SPLIT) * 64) / 4, 128>>>(pop, pmp, plp, oh, ol);

    // 4. Output projection (wo = weight index 3), fp32 store
    dim3 gg(DMODEL / 128, SEQ / 128, 1);
    gemm_bf<0><<<gg, 256, gemm_smem>>>(oh, ol, wh + (size_t)3 * WELEM, wl + (size_t)3 * WELEM,
                                       out, nullptr, nullptr, nullptr, nullptr,
                                       nullptr, nullptr, nullptr, nullptr, nullptr);
}

// round 17
// speedup vs baseline: 1.5257x; 1.0160x over previous
#include <cuda_runtime.h>
#include <cuda_bf16.h>
#include <math.h>
#include <stdint.h>

using bf16 = __nv_bfloat16;

constexpr int SEQ    = 4096;
constexpr int DMODEL = 768;
constexpr int NH     = 12;
constexpr int DH     = 64;
constexpr int HALF   = DH / 2;   // 32
constexpr int WELEM  = DMODEL * DMODEL;

// Q pre-scale: (1/sqrt(64)) * log2(e)  -> softmax computed in exp2 domain
constexpr float QSCALE_LOG2 = 0.125f * 1.44269504088896340736f;

// attention work split: qb in [32,63] handled by 2 CTAs (KV halves) + merge
constexpr int QB_SPLIT   = 32;
constexpr int NSPLIT_CTA = (64 - QB_SPLIT) * NH * 2;   // 768
constexpr int NNORM_CTA  = QB_SPLIT * NH;              // 384

// Scratch (device globals; no runtime allocation allowed)
__device__ bf16  g_xh[SEQ * DMODEL];
__device__ bf16  g_xl[SEQ * DMODEL];
__device__ bf16  g_wh[4 * WELEM];
__device__ bf16  g_wl[4 * WELEM];
__device__ bf16  g_oh[SEQ * DMODEL];
__device__ bf16  g_ol[SEQ * DMODEL];
__device__ bf16  g_qh[NH * SEQ * DH];
__device__ bf16  g_ql[NH * SEQ * DH];
__device__ bf16  g_kh[NH * SEQ * DH];
__device__ bf16  g_kl[NH * SEQ * DH];
__device__ bf16  g_vh[NH * SEQ * DH];
__device__ bf16  g_vl[NH * SEQ * DH];
__device__ float g_cos[SEQ * HALF];
__device__ float g_sin[SEQ * HALF];
// split-KV partials: 768 slots x 64 rows x 64 cols + m/l per row
__device__ float g_po[NSPLIT_CTA * 64 * 64];
__device__ float g_pm[NSPLIT_CTA * 64];
__device__ float g_pl[NSPLIT_CTA * 64];
// split-K partials for the output projection
__device__ float g_pc[2 * SEQ * DMODEL];

// ---------------------------------------------------------------------------
// bf16 split helpers
// ---------------------------------------------------------------------------
__device__ __forceinline__ void split_store_pair(bf16* __restrict__ hi_arr,
                                                 bf16* __restrict__ lo_arr,
                                                 size_t idx, float a, float b)
{
    __nv_bfloat162 h = __floats2bfloat162_rn(a, b);
    float ha = __bfloat162float(h.x);
    float hb = __bfloat162float(h.y);
    __nv_bfloat162 l = __floats2bfloat162_rn(a - ha, b - hb);
    *reinterpret_cast<__nv_bfloat162*>(hi_arr + idx) = h;
    *reinterpret_cast<__nv_bfloat162*>(lo_arr + idx) = l;
}

__device__ __forceinline__ void splitpack(float a, float b,
                                          uint32_t& hi, uint32_t& lo)
{
    __nv_bfloat162 h = __floats2bfloat162_rn(a, b);
    float ha = __bfloat162float(h.x);
    float hb = __bfloat162float(h.y);
    __nv_bfloat162 l = __floats2bfloat162_rn(a - ha, b - hb);
    hi = *reinterpret_cast<uint32_t*>(&h);
    lo = *reinterpret_cast<uint32_t*>(&l);
}

__device__ __forceinline__ void cvt8_split(const float4& p0, const float4& p1,
                                           uint4& hi, uint4& lo)
{
    uint32_t h0, l0, h1, l1, h2, l2, h3, l3;
    splitpack(p0.x, p0.y, h0, l0);
    splitpack(p0.z, p0.w, h1, l1);
    splitpack(p1.x, p1.y, h2, l2);
    splitpack(p1.z, p1.w, h3, l3);
    hi = make_uint4(h0, h1, h2, h3);
    lo = make_uint4(l0, l1, l2, l3);
}

__device__ __forceinline__ float ex2f(float x)
{
    float y;
    asm("ex2.approx.ftz.f32 %0, %1;" : "=f"(y) : "f"(x));
    return y;
}

// ---------------------------------------------------------------------------
// One-time fp32 -> bf16 hi/lo conversion of x and the 4 weights + RoPE cache.
// grid.y: 0=x, 1..4=weights, 5=rope cache.
// ---------------------------------------------------------------------------
__global__ __launch_bounds__(256)
void convert_split_kernel(const float* __restrict__ x,
                          const float* __restrict__ wq, const float* __restrict__ wk,
                          const float* __restrict__ wv, const float* __restrict__ wo,
                          bf16* __restrict__ xh, bf16* __restrict__ xl,
                          bf16* __restrict__ wh, bf16* __restrict__ wl,
                          float* __restrict__ cc, float* __restrict__ ss)
{
    int y = blockIdx.y;
    if (y == 5) {
        int i = blockIdx.x * 256 + threadIdx.x;
        if (i >= SEQ * HALF) return;
        int p = i >> 5;
        int k = i & 31;
        float expo = -2.0f * (float)k / (float)DH;
        float invf = powf(10000.0f, expo);
        float ang  = (float)p * invf;
        cc[i] = cosf(ang);
        ss[i] = sinf(ang);
        return;
    }
    const float* src;
    bf16 *dh, *dl;
    int n;
    if (y == 0) { src = x;  dh = xh; dl = xl; n = SEQ * DMODEL; }
    else {
        src = (y == 1) ? wq : (y == 2) ? wk : (y == 3) ? wv : wo;
        dh = wh + (size_t)(y - 1) * WELEM;
        dl = wl + (size_t)(y - 1) * WELEM;
        n = WELEM;
    }
    int i = (blockIdx.x * 256 + threadIdx.x) * 8;
    if (i >= n) return;
    float4 a = *(const float4*)(src + i);
    float4 b = *(const float4*)(src + i + 4);
    uint4 hi, lo;
    cvt8_split(a, b, hi, lo);
    *(uint4*)(dh + i) = hi;
    *(uint4*)(dl + i) = lo;
}

// ---------------------------------------------------------------------------
// mma / ldmatrix / cp.async wrappers
// ---------------------------------------------------------------------------
__device__ __forceinline__ void ldsm4(uint32_t* r, uint32_t addr)
{
    asm volatile("ldmatrix.sync.aligned.m8n8.x4.shared.b16 {%0,%1,%2,%3}, [%4];"
        : "=r"(r[0]), "=r"(r[1]), "=r"(r[2]), "=r"(r[3]) : "r"(addr));
}
__device__ __forceinline__ void ldsm4t(uint32_t* r, uint32_t addr)
{
    asm volatile("ldmatrix.sync.aligned.m8n8.x4.trans.shared.b16 {%0,%1,%2,%3}, [%4];"
        : "=r"(r[0]), "=r"(r[1]), "=r"(r[2]), "=r"(r[3]) : "r"(addr));
}
__device__ __forceinline__ void mma16816(float* d, const uint32_t* a, const uint32_t* b)
{
    asm volatile(
        "mma.sync.aligned.m16n8k16.row.col.f32.bf16.bf16.f32 "
        "{%0,%1,%2,%3}, {%4,%5,%6,%7}, {%8,%9}, {%0,%1,%2,%3};"
        : "+f"(d[0]), "+f"(d[1]), "+f"(d[2]), "+f"(d[3])
        : "r"(a[0]), "r"(a[1]), "r"(a[2]), "r"(a[3]), "r"(b[0]), "r"(b[1]));
}
__device__ __forceinline__ void cp16(uint32_t dst, const void* src)
{
    asm volatile("cp.async.cg.shared.global [%0], [%1], 16;"
        :: "r"(dst), "l"(src));
}
#define CP_COMMIT() asm volatile("cp.async.commit_group;")
#define CP_WAIT(n)  asm volatile("cp.async.wait_group %0;" :: "n"(n))

// ---------------------------------------------------------------------------
// Split-bf16 NT GEMM on pre-split inputs.
// MODE 1: QKV by blockIdx.z; RoPE for z<2; split scatter. (champion, unchanged)
// ---------------------------------------------------------------------------
template<int MODE>
__global__ __launch_bounds__(256, 2)
void gemm_bf(const bf16* __restrict__ Agh, const bf16* __restrict__ Agl,
             const bf16* __restrict__ Wgh, const bf16* __restrict__ Wgl,
             float* __restrict__ Cout,
             bf16* __restrict__ qh, bf16* __restrict__ ql,
             bf16* __restrict__ kh, bf16* __restrict__ kl,
             bf16* __restrict__ vh, bf16* __restrict__ vl,
             const int* __restrict__ pos,
             const float* __restrict__ cosc, const float* __restrict__ sinc)
{
    constexpr int KD  = 768;
    constexpr int NCH = KD / 32;  // 24
    extern __shared__ __align__(128) uint8_t sm[];
    const uint32_t smb = (uint32_t)__cvta_generic_to_shared(sm);

    const int tid  = threadIdx.x;
    const int wid  = tid >> 5;
    const int lane = tid & 31;
    const int z    = (MODE == 1) ? blockIdx.z : 0;
    const bf16* Bgh = Wgh + (size_t)z * WELEM;
    const bf16* Bgl = Wgl + (size_t)z * WELEM;
    const int m0   = blockIdx.y * 128;
    const int n0   = blockIdx.x * 128;
    const int wm   = wid >> 1;
    const int wn   = wid & 1;

    float acc[2][8][4];
    #pragma unroll
    for (int m = 0; m < 2; m++)
        #pragma unroll
        for (int n = 0; n < 8; n++)
            #pragma unroll
            for (int j = 0; j < 4; j++) acc[m][n][j] = 0.0f;

    auto cp_chunk = [&](int c, int s) {
        uint32_t base = smb + s * 32768;
        int kb = c * 32;
        #pragma unroll
        for (int it = 0; it < 2; it++) {
            int i   = it * 256 + tid;
            int row = i >> 2, o = i & 3;
            uint32_t off = (uint32_t)(row * 64 + ((o ^ (row & 3)) << 4));
            size_t ga = (size_t)(m0 + row) * KD + kb + o * 8;
            size_t gb = (size_t)(n0 + row) * KD + kb + o * 8;
            cp16(base + off,         Agh + ga);
            cp16(base +  8192 + off, Agl + ga);
            cp16(base + 16384 + off, Bgh + gb);
            cp16(base + 24576 + off, Bgl + gb);
        }
    };

    cp_chunk(0, 0); CP_COMMIT();
    cp_chunk(1, 1); CP_COMMIT();

    for (int c = 0; c < NCH; c++) {
        if (c < NCH - 1) { CP_WAIT(1); } else { CP_WAIT(0); }
        __syncthreads();
        if (c + 2 < NCH) { cp_chunk(c + 2, (c + 2) % 3); CP_COMMIT(); }

        const uint32_t sb = smb + (c % 3) * 32768;
        #pragma unroll
        for (int kt = 0; kt < 2; kt++) {
            uint32_t ah[2][4], al[2][4];
            #pragma unroll
            for (int m = 0; m < 2; m++) {
                int row = wm * 32 + m * 16 + (lane & 15);
                int ch  = kt * 2 + (lane >> 4);
                uint32_t off = (uint32_t)(row * 64 + ((ch ^ (row & 3)) << 4));
                ldsm4(ah[m], sb + off);
                ldsm4(al[m], sb + 8192 + off);
            }
            uint32_t bh4[4][4], bl4[4][4];
            #pragma unroll
            for (int np = 0; np < 4; np++) {
                int row = wn * 64 + np * 16 + (lane & 7) + ((lane >> 4) << 3);
                int ch  = kt * 2 + ((lane >> 3) & 1);
                uint32_t off = (uint32_t)(row * 64 + ((ch ^ (row & 3)) << 4));
                ldsm4(bh4[np], sb + 16384 + off);
                ldsm4(bl4[np], sb + 24576 + off);
            }
            #pragma unroll
            for (int m = 0; m < 2; m++)
                #pragma unroll
                for (int np = 0; np < 4; np++) {
                    mma16816(acc[m][2*np],     ah[m], bh4[np]);
                    mma16816(acc[m][2*np + 1], ah[m], bh4[np] + 2);
                }
            #pragma unroll
            for (int m = 0; m < 2; m++)
                #pragma unroll
                for (int np = 0; np < 4; np++) {
                    mma16816(acc[m][2*np],     ah[m], bl4[np]);
                    mma16816(acc[m][2*np + 1], ah[m], bl4[np] + 2);
                }
            #pragma unroll
            for (int m = 0; m < 2; m++)
                #pragma unroll
                for (int np = 0; np < 4; np++) {
                    mma16816(acc[m][2*np],     al[m], bh4[np]);
                    mma16816(acc[m][2*np + 1], al[m], bh4[np] + 2);
                }
        }
    }

    // ---- epilogue ----
    const int rbase = m0 + wm * 32 + (lane >> 2);
    const int cbase = n0 + wn * 64 + (lane & 3) * 2;

    if (MODE == 0) {
        #pragma unroll
        for (int m = 0; m < 2; m++)
            #pragma unroll
            for (int nt = 0; nt < 8; nt++) {
                const float* v = acc[m][nt];
                int r = rbase + m * 16;
                int c = cbase + nt * 8;
                *(float2*)&Cout[(size_t)r * DMODEL + c]       = make_float2(v[0], v[1]);
                *(float2*)&Cout[(size_t)(r + 8) * DMODEL + c] = make_float2(v[2], v[3]);
            }
    } else {
        bf16* hi_arr = (z == 0) ? qh : (z == 1) ? kh : vh;
        bf16* lo_arr = (z == 0) ? ql : (z == 1) ? kl : vl;
        const float scale = (z == 0) ? QSCALE_LOG2 : 1.0f;

        #pragma unroll
        for (int m = 0; m < 2; m++) {
            int r = rbase + m * 16;
            if (z < 2) {
                int p0 = pos[r], p1 = pos[r + 8];
                const float* cr0 = cosc + (size_t)p0 * HALF;
                const float* sr0 = sinc + (size_t)p0 * HALF;
                const float* cr1 = cosc + (size_t)p1 * HALF;
                const float* sr1 = sinc + (size_t)p1 * HALF;
                #pragma unroll
                for (int nt = 0; nt < 8; nt++) {
                    const float* v = acc[m][nt];
                    int c  = cbase + nt * 8;
                    int dh = c & 63;
                    int hh = c >> 6;
                    float cc = cr0[dh >> 1], ssv = sr0[dh >> 1];
                    float re = (v[0] * cc - v[1] * ssv) * scale;
                    float ro = (v[0] * ssv + v[1] * cc) * scale;
                    split_store_pair(hi_arr, lo_arr,
                                     ((size_t)hh * SEQ + r) * DH + dh, re, ro);
                    cc = cr1[dh >> 1]; ssv = sr1[dh >> 1];
                    re = (v[2] * cc - v[3] * ssv) * scale;
                    ro = (v[2] * ssv + v[3] * cc) * scale;
                    split_store_pair(hi_arr, lo_arr,
                                     ((size_t)hh * SEQ + r + 8) * DH + dh, re, ro);
                }
            } else {
                #pragma unroll
                for (int nt = 0; nt < 8; nt++) {
                    const float* v = acc[m][nt];
                    int c  = cbase + nt * 8;
                    int dh = c & 63;
                    int hh = c >> 6;
                    split_store_pair(hi_arr, lo_arr,
                                     ((size_t)hh * SEQ + r) * DH + dh, v[0], v[1]);
                    split_store_pair(hi_arr, lo_arr,
                                     ((size_t)hh * SEQ + r + 8) * DH + dh, v[2], v[3]);
                }
            }
        }
    }
}

// ---------------------------------------------------------------------------
// Split-K output projection body: fully static K-range [C0, C0+12).
// Same mainloop structure as the champion; epilogue = fp32 partial store.
// ---------------------------------------------------------------------------
template<int C0>
__device__ __forceinline__
void gemm_sk_body(const bf16* __restrict__ Agh, const bf16* __restrict__ Agl,
                  const bf16* __restrict__ Bgh, const bf16* __restrict__ Bgl,
                  float* __restrict__ dst, uint8_t* sm)
{
    constexpr int KD = 768;
    constexpr int C1 = C0 + 12;
    const uint32_t smb = (uint32_t)__cvta_generic_to_shared(sm);

    const int tid  = threadIdx.x;
    const int wid  = tid >> 5;
    const int lane = tid & 31;
    const int m0   = blockIdx.y * 128;
    const int n0   = blockIdx.x * 128;
    const int wm   = wid >> 1;
    const int wn   = wid & 1;

    float acc[2][8][4];
    #pragma unroll
    for (int m = 0; m < 2; m++)
        #pragma unroll
        for (int n = 0; n < 8; n++)
            #pragma unroll
            for (int j = 0; j < 4; j++) acc[m][n][j] = 0.0f;

    auto cp_chunk = [&](int c, int s) {
        uint32_t base = smb + s * 32768;
        int kb = c * 32;
        #pragma unroll
        for (int it = 0; it < 2; it++) {
            int i   = it * 256 + tid;
            int row = i >> 2, o = i & 3;
            uint32_t off = (uint32_t)(row * 64 + ((o ^ (row & 3)) << 4));
            size_t ga = (size_t)(m0 + row) * KD + kb + o * 8;
            size_t gb = (size_t)(n0 + row) * KD + kb + o * 8;
            cp16(base + off,         Agh + ga);
            cp16(base +  8192 + off, Agl + ga);
            cp16(base + 16384 + off, Bgh + gb);
            cp16(base + 24576 + off, Bgl + gb);
        }
    };

    cp_chunk(C0, C0 % 3);           CP_COMMIT();
    cp_chunk(C0 + 1, (C0 + 1) % 3); CP_COMMIT();

    #pragma unroll 1
    for (int c = C0; c < C1; c++) {
        if (c < C1 - 1) { CP_WAIT(1); } else { CP_WAIT(0); }
        __syncthreads();
        if (c + 2 < C1) { cp_chunk(c + 2, (c + 2) % 3); CP_COMMIT(); }

        const uint32_t sb = smb + (c % 3) * 32768;
        #pragma unroll
        for (int kt = 0; kt < 2; kt++) {
            uint32_t ah[2][4], al[2][4];
            #pragma unroll
            for (int m = 0; m < 2; m++) {
                int row = wm * 32 + m * 16 + (lane & 15);
                int ch  = kt * 2 + (lane >> 4);
                uint32_t off = (uint32_t)(row * 64 + ((ch ^ (row & 3)) << 4));
                ldsm4(ah[m], sb + off);
                ldsm4(al[m], sb + 8192 + off);
            }
            uint32_t bh4[4][4], bl4[4][4];
            #pragma unroll
            for (int np = 0; np < 4; np++) {
                int row = wn * 64 + np * 16 + (lane & 7) + ((lane >> 4) << 3);
                int ch  = kt * 2 + ((lane >> 3) & 1);
                uint32_t off = (uint32_t)(row * 64 + ((ch ^ (row & 3)) << 4));
                ldsm4(bh4[np], sb + 16384 + off);
                ldsm4(bl4[np], sb + 24576 + off);
            }
            #pragma unroll
            for (int m = 0; m < 2; m++)
                #pragma unroll
                for (int np = 0; np < 4; np++) {
                    mma16816(acc[m][2*np],     ah[m], bh4[np]);
                    mma16816(acc[m][2*np + 1], ah[m], bh4[np] + 2);
                }
            #pragma unroll
            for (int m = 0; m < 2; m++)
                #pragma unroll
                for (int np = 0; np < 4; np++) {
                    mma16816(acc[m][2*np],     ah[m], bl4[np]);
                    mma16816(acc[m][2*np + 1], ah[m], bl4[np] + 2);
                }
            #pragma unroll
            for (int m = 0; m < 2; m++)
                #pragma unroll
                for (int np = 0; np < 4; np++) {
                    mma16816(acc[m][2*np],     al[m], bh4[np]);
                    mma16816(acc[m][2*np + 1], al[m], bh4[np] + 2);
                }
        }
    }

    const int rbase = m0 + wm * 32 + (lane >> 2);
    const int cbase = n0 + wn * 64 + (lane & 3) * 2;
    #pragma unroll
    for (int m = 0; m < 2; m++)
        #pragma unroll
        for (int nt = 0; nt < 8; nt++) {
            const float* v = acc[m][nt];
            int r = rbase + m * 16;
            int c = cbase + nt * 8;
            *(float2*)&dst[(size_t)r * DMODEL + c]       = make_float2(v[0], v[1]);
            *(float2*)&dst[(size_t)(r + 8) * DMODEL + c] = make_float2(v[2], v[3]);
        }
}

__global__ __launch_bounds__(256, 2)
void gemm_out_sk(const bf16* __restrict__ Agh, const bf16* __restrict__ Agl,
                 const bf16* __restrict__ Bgh, const bf16* __restrict__ Bgl,
                 float* __restrict__ pc)
{
    extern __shared__ __align__(128) uint8_t sm[];
    if (blockIdx.z == 0)
        gemm_sk_body<0>(Agh, Agl, Bgh, Bgl, pc, sm);
    else
        gemm_sk_body<12>(Agh, Agl, Bgh, Bgl, pc + (size_t)SEQ * DMODEL, sm);
}

// ---------------------------------------------------------------------------
// Reduce the two split-K partials into the final output (deterministic).
// ---------------------------------------------------------------------------
__global__ __launch_bounds__(256)
void reduce_add_kernel(const float* __restrict__ p, float* __restrict__ out)
{
    int i = (blockIdx.x * 256 + threadIdx.x) * 4;
    float4 a = *(const float4*)(p + i);
    float4 b = *(const float4*)(p + SEQ * DMODEL + i);
    *(float4*)(out + i) = make_float4(a.x + b.x, a.y + b.y, a.z + b.z, a.w + b.w);
}

// ---------------------------------------------------------------------------
// Flash attention, split-bf16 mma, 64 q-rows/CTA, 3 CTAs/SM.  (champion exact)
// ---------------------------------------------------------------------------
__global__ __launch_bounds__(128, 3)
void attn_mma(const bf16* __restrict__ Qh, const bf16* __restrict__ Ql,
              const bf16* __restrict__ Kh, const bf16* __restrict__ Kl,
              const bf16* __restrict__ Vh, const bf16* __restrict__ Vl,
              bf16* __restrict__ Oh, bf16* __restrict__ Ol,
              float* __restrict__ po, float* __restrict__ pm,
              float* __restrict__ pl)
{
    extern __shared__ __align__(128) uint8_t sm[];

    const int bx  = blockIdx.x;
    int h, qb, t0, t1, pslot;
    if (bx < NSPLIT_CTA) {
        int qi = bx / (NH * 2);        // 0..31, qb = 63 - qi (big first)
        int r  = bx % (NH * 2);
        h = r >> 1;
        int half = r & 1;
        qb = 63 - qi;
        int nt  = qb + 1;
        int ntA = (nt + 1) >> 1;
        t0 = half ? ntA : 0;
        t1 = half ? nt  : ntA;
        pslot = h * 64 + (qb - QB_SPLIT) * 2 + half;
    } else {
        int j = bx - NSPLIT_CTA;
        qb = QB_SPLIT - 1 - j / NH;    // 31..0 big first
        h = j % NH;
        t0 = 0;
        t1 = qb + 1;
        pslot = -1;
    }
    const int q0  = qb * 64;
    const int tid = threadIdx.x;
    const int wid = tid >> 5;
    const int lane = tid & 31;

    const size_t hoff = (size_t)h * SEQ * DH;
    const uint32_t smbase = (uint32_t)__cvta_generic_to_shared(sm);

    {
        const uint8_t* qsH = (const uint8_t*)(Qh + hoff + (size_t)q0 * DH);
        const uint8_t* qsL = (const uint8_t*)(Ql + hoff + (size_t)q0 * DH);
        for (int i = tid; i < 512; i += 128) {
            int row = i >> 3, ch = i & 7;
            uint32_t off = row * 128 + ((ch ^ (row & 7)) << 4);
            *(uint4*)(sm + off)        = *(const uint4*)(qsH + row * 128 + ch * 16);
            *(uint4*)(sm + 8192 + off) = *(const uint4*)(qsL + row * 128 + ch * 16);
        }
    }
    __syncthreads();

    uint32_t qfh[4][4], qfl[4][4];
    {
        int row = wid * 16 + (lane & 15);
        int chs = lane >> 4;
        #pragma unroll
        for (int kt = 0; kt < 4; kt++) {
            int ch = 2 * kt + chs;
            uint32_t off = row * 128 + ((ch ^ (row & 7)) << 4);
            ldsm4(qfh[kt], smbase + off);
            ldsm4(qfl[kt], smbase + 8192 + off);
        }
    }
    __syncthreads();

    const uint8_t* kHp = (const uint8_t*)(Kh + hoff);
    const uint8_t* kLp = (const uint8_t*)(Kl + hoff);
    const uint8_t* vHp = (const uint8_t*)(Vh + hoff);
    const uint8_t* vLp = (const uint8_t*)(Vl + hoff);

    auto issue_tile = [&](int k0, int stage) {
        uint32_t sb = smbase + stage * 32768;
        #pragma unroll
        for (int i = tid; i < 512; i += 128) {
            int row = i >> 3, ch = i & 7;
            uint32_t off = row * 128 + ((ch ^ (row & 7)) << 4);
            size_t g = (size_t)(k0 + row) * 128 + ch * 16;
            cp16(sb + off,         kHp + g);
            cp16(sb +  8192 + off, kLp + g);
            cp16(sb + 16384 + off, vHp + g);
            cp16(sb + 24576 + off, vLp + g);
        }
    };

    float o[8][4];
    #pragma unroll
    for (int i = 0; i < 8; i++)
        #pragma unroll
        for (int j = 0; j < 4; j++) o[i][j] = 0.0f;
    float mr0 = -1e30f, mr1 = -1e30f, lr0 = 0.0f, lr1 = 0.0f;

    const int rmax = q0 + wid * 16 + 15;
    const int r0g  = q0 + wid * 16 + (lane >> 2);

    issue_tile(t0 * 64, t0 & 1);
    CP_COMMIT();

    for (int t = t0; t < t1; t++) {
        const int k0 = t * 64;

        if (t + 1 < t1) {
            issue_tile((t + 1) * 64, (t + 1) & 1);
            CP_COMMIT();
            CP_WAIT(1);
        } else {
            CP_WAIT(0);
        }
        __syncthreads();

        if (k0 <= rmax) {
            const uint32_t sb = smbase + (t & 1) * 32768;

            float s[8][4];
            #pragma unroll
            for (int nt = 0; nt < 8; nt++)
                #pragma unroll
                for (int j = 0; j < 4; j++) s[nt][j] = 0.0f;

            #pragma unroll
            for (int nt = 0; nt < 8; nt++) {
                uint32_t bh[8], bl[8];
                int row = nt * 8 + (lane & 7);
                {
                    int ch = lane >> 3;
                    uint32_t off = row * 128 + ((ch ^ (row & 7)) << 4);
                    ldsm4(bh,     sb + off);
                    ldsm4(bl,     sb + 8192 + off);
                    int ch2 = 4 + (lane >> 3);
                    uint32_t off2 = row * 128 + ((ch2 ^ (row & 7)) << 4);
                    ldsm4(bh + 4, sb + off2);
                    ldsm4(bl + 4, sb + 8192 + off2);
                }
                #pragma unroll
                for (int kt = 0; kt < 4; kt++) {
                    mma16816(s[nt], qfh[kt], bh + 2 * kt);
                    mma16816(s[nt], qfh[kt], bl + 2 * kt);
                    mma16816(s[nt], qfl[kt], bh + 2 * kt);
                }
            }

            if (k0 + 63 > q0 + wid * 16) {
                #pragma unroll
                for (int nt = 0; nt < 8; nt++) {
                    int c0 = k0 + nt * 8 + ((lane & 3) << 1);
                    if (c0     > r0g)     s[nt][0] = -1e30f;
                    if (c0 + 1 > r0g)     s[nt][1] = -1e30f;
                    if (c0     > r0g + 8) s[nt][2] = -1e30f;
                    if (c0 + 1 > r0g + 8) s[nt][3] = -1e30f;
                }
            }

            float mx0 = -1e30f, mx1 = -1e30f;
            #pragma unroll
            for (int nt = 0; nt < 8; nt++) {
                mx0 = fmaxf(mx0, fmaxf(s[nt][0], s[nt][1]));
                mx1 = fmaxf(mx1, fmaxf(s[nt][2], s[nt][3]));
            }
            mx0 = fmaxf(mx0, __shfl_xor_sync(0xffffffffu, mx0, 1));
            mx0 = fmaxf(mx0, __shfl_xor_sync(0xffffffffu, mx0, 2));
            mx1 = fmaxf(mx1, __shfl_xor_sync(0xffffffffu, mx1, 1));
            mx1 = fmaxf(mx1, __shfl_xor_sync(0xffffffffu, mx1, 2));

            float mn0 = fmaxf(mr0, mx0), mn1 = fmaxf(mr1, mx1);
            float c0 = ex2f(mr0 - mn0), c1 = ex2f(mr1 - mn1);
            mr0 = mn0; mr1 = mn1;

            float sum0 = 0.0f, sum1 = 0.0f;
            #pragma unroll
            for (int nt = 0; nt < 8; nt++) {
                s[nt][0] = ex2f(s[nt][0] - mn0);
                s[nt][1] = ex2f(s[nt][1] - mn0);
                s[nt][2] = ex2f(s[nt][2] - mn1);
                s[nt][3] = ex2f(s[nt][3] - mn1);
                sum0 += s[nt][0] + s[nt][1];
                sum1 += s[nt][2] + s[nt][3];
            }
            lr0 = lr0 * c0 + sum0;
            lr1 = lr1 * c1 + sum1;

            #pragma unroll
            for (int dt = 0; dt < 8; dt++) {
                o[dt][0] *= c0; o[dt][1] *= c0;
                o[dt][2] *= c1; o[dt][3] *= c1;
            }

            uint32_t pfh[4][4], pfl[4][4];
            #pragma unroll
            for (int kt = 0; kt < 4; kt++) {
                splitpack(s[2*kt][0],   s[2*kt][1],   pfh[kt][0], pfl[kt][0]);
                splitpack(s[2*kt][2],   s[2*kt][3],   pfh[kt][1], pfl[kt][1]);
                splitpack(s[2*kt+1][0], s[2*kt+1][1], pfh[kt][2], pfl[kt][2]);
                splitpack(s[2*kt+1][2], s[2*kt+1][3], pfh[kt][3], pfl[kt][3]);
            }

            #pragma unroll
            for (int kt = 0; kt < 4; kt++) {
                #pragma unroll
                for (int dq = 0; dq < 2; dq++) {
                    uint32_t vh4[2][4], vl4[2][4];
                    #pragma unroll
                    for (int d = 0; d < 2; d++) {
                        int dp = dq * 2 + d;
                        int vrow = kt * 16 + (lane & 15);
                        int ch = 2 * dp + (lane >> 4);
                        uint32_t off = vrow * 128 + ((ch ^ (vrow & 7)) << 4);
                        ldsm4t(vh4[d], sb + 16384 + off);
                        ldsm4t(vl4[d], sb + 24576 + off);
                    }
                    #pragma unroll
                    for (int d = 0; d < 2; d++) {
                        int dp = dq * 2 + d;
                        mma16816(o[2*dp],     pfh[kt], vh4[d]);
                        mma16816(o[2*dp + 1], pfh[kt], vh4[d] + 2);
                        mma16816(o[2*dp],     pfh[kt], vl4[d]);
                        mma16816(o[2*dp + 1], pfh[kt], vl4[d] + 2);
                        mma16816(o[2*dp],     pfl[kt], vh4[d]);
                        mma16816(o[2*dp + 1], pfl[kt], vh4[d] + 2);
                    }
                }
            }
        }
        __syncthreads();
    }

    // deferred cross-lane l reduction (c factors are row-uniform)
    lr0 += __shfl_xor_sync(0xffffffffu, lr0, 1);
    lr0 += __shfl_xor_sync(0xffffffffu, lr0, 2);
    lr1 += __shfl_xor_sync(0xffffffffu, lr1, 1);
    lr1 += __shfl_xor_sync(0xffffffffu, lr1, 2);

    if (pslot < 0) {
        float i0 = 1.0f / lr0, i1 = 1.0f / lr1;
        int cb = h * DH + ((lane & 3) << 1);
        #pragma unroll
        for (int dt = 0; dt < 8; dt++) {
            split_store_pair(Oh, Ol, (size_t)r0g * DMODEL + cb + dt * 8,
                             o[dt][0] * i0, o[dt][1] * i0);
            split_store_pair(Oh, Ol, (size_t)(r0g + 8) * DMODEL + cb + dt * 8,
                             o[dt][2] * i1, o[dt][3] * i1);
        }
    } else {
        // unnormalized partial: o, m, l (log2 domain)
        float* pob = po + (size_t)pslot * 4096;
        int rA = wid * 16 + (lane >> 2);
        int cb2 = (lane & 3) * 2;
        #pragma unroll
        for (int dt = 0; dt < 8; dt++) {
            *(float2*)&pob[rA * 64 + cb2 + dt * 8]       = make_float2(o[dt][0], o[dt][1]);
            *(float2*)&pob[(rA + 8) * 64 + cb2 + dt * 8] = make_float2(o[dt][2], o[dt][3]);
        }
        if ((lane & 3) == 0) {
            pm[pslot * 64 + rA]     = mr0;
            pl[pslot * 64 + rA]     = lr0;
            pm[pslot * 64 + rA + 8] = mr1;
            pl[pslot * 64 + rA + 8] = lr1;
        }
    }
}

// ---------------------------------------------------------------------------
// Merge split-KV partials: one warp per row.
// ---------------------------------------------------------------------------
__global__ __launch_bounds__(128)
void attn_merge(const float* __restrict__ po, const float* __restrict__ pm,
                const float* __restrict__ pl,
                bf16* __restrict__ Oh, bf16* __restrict__ Ol)
{
    int row  = blockIdx.x * 4 + (threadIdx.x >> 5);   // 0 .. 24575
    int lane = threadIdx.x & 31;
    int h    = row / ((64 - QB_SPLIT) * 64);
    int rr   = row % ((64 - QB_SPLIT) * 64);
    int qrel = rr >> 6;
    int r    = rr & 63;

    int slotA = h * 64 + qrel * 2;
    const float* poA = po + (size_t)slotA * 4096 + r * 64;
    const float* poB = poA + 4096;
    float mA = pm[slotA * 64 + r], mB = pm[(slotA + 1) * 64 + r];
    float lA = pl[slotA * 64 + r], lB = pl[(slotA + 1) * 64 + r];
    float M  = fmaxf(mA, mB);
    float cA = ex2f(mA - M), cB = ex2f(mB - M);
    float inv = 1.0f / (cA * lA + cB * lB);

    int srow = (QB_SPLIT + qrel) * 64 + r;
    int c    = lane * 2;
    float a = (cA * poA[c]     + cB * poB[c])     * inv;
    float b = (cA * poA[c + 1] + cB * poB[c + 1]) * inv;
    split_store_pair(Oh, Ol, (size_t)srow * DMODEL + h * DH + c, a, b);
}

// ---------------------------------------------------------------------------
// kernel_launch — graph-capturable, allocation-free.
// ---------------------------------------------------------------------------
extern "C" void kernel_launch(void* const* d_in, const int* in_sizes, int n_in,
                              void* d_out, int out_size)
{
    const float* x   = (const float*)d_in[0];
    const float* wq  = (const float*)d_in[1];
    const float* wk  = (const float*)d_in[2];
    const float* wv  = (const float*)d_in[3];
    const float* wo  = (const float*)d_in[4];
    const int*   pos = (const int*)d_in[5];
    float* out = (float*)d_out;

    bf16 *xh, *xl, *wh, *wl, *oh, *ol;
    bf16 *qh, *ql, *kh, *kl, *vh, *vl;
    float *cp, *sp, *pop, *pmp, *plp, *pcp;
    cudaGetSymbolAddress((void**)&xh, g_xh);
    cudaGetSymbolAddress((void**)&xl, g_xl);
    cudaGetSymbolAddress((void**)&wh, g_wh);
    cudaGetSymbolAddress((void**)&wl, g_wl);
    cudaGetSymbolAddress((void**)&oh, g_oh);
    cudaGetSymbolAddress((void**)&ol, g_ol);
    cudaGetSymbolAddress((void**)&qh, g_qh);
    cudaGetSymbolAddress((void**)&ql, g_ql);
    cudaGetSymbolAddress((void**)&kh, g_kh);
    cudaGetSymbolAddress((void**)&kl, g_kl);
    cudaGetSymbolAddress((void**)&vh, g_vh);
    cudaGetSymbolAddress((void**)&vl, g_vl);
    cudaGetSymbolAddress((void**)&cp, g_cos);
    cudaGetSymbolAddress((void**)&sp, g_sin);
    cudaGetSymbolAddress((void**)&pop, g_po);
    cudaGetSymbolAddress((void**)&pmp, g_pm);
    cudaGetSymbolAddress((void**)&plp, g_pl);
    cudaGetSymbolAddress((void**)&pcp, g_pc);

    const int gemm_smem = 3 * 32768;   // 98304
    const int attn_smem = 65536;
    cudaFuncSetAttribute(gemm_bf<1>,  cudaFuncAttributeMaxDynamicSharedMemorySize, gemm_smem);
    cudaFuncSetAttribute(gemm_out_sk, cudaFuncAttributeMaxDynamicSharedMemorySize, gemm_smem);
    cudaFuncSetAttribute(attn_mma,    cudaFuncAttributeMaxDynamicSharedMemorySize, attn_smem);

    // 1. hi/lo split of x + weights, and RoPE cache (fused launch)
    convert_split_kernel<<<dim3((SEQ * DMODEL / 8 + 255) / 256, 6), 256>>>(
        x, wq, wk, wv, wo, xh, xl, wh, wl, cp, sp);

    // 2. QKV projections (Q scaled by 0.125*log2e for exp2-domain softmax)
    dim3 gq(DMODEL / 128, SEQ / 128, 3);
    gemm_bf<1><<<gq, 256, gemm_smem>>>(xh, xl, wh, wl, nullptr,
                                       qh, ql, kh, kl, vh, vl, pos, cp, sp);

    // 3. Causal flash attention: unified grid, big KV-halves first
    attn_mma<<<NSPLIT_CTA + NNORM_CTA, 128, attn_smem>>>(
        qh, ql, kh, kl, vh, vl, oh, ol, pop, pmp, plp);

    // 3b. Merge split-KV partials
    attn_merge<<<(NH * (64 - QB_SPLIT) * 64) / 4, 128>>>(pop, pmp, plp, oh, ol);

    // 4. Output projection, split-K 2-way (static bounds per z), then reduce
    dim3 gg(DMODEL / 128, SEQ / 128, 2);
    gemm_out_sk<<<gg, 256, gemm_smem>>>(oh, ol,
                                        wh + (size_t)3 * WELEM, wl + (size_t)3 * WELEM,
                                        pcp);
    reduce_add_kernel<<<SEQ * DMODEL / 4 / 256, 256>>>(pcp, out);
}